// round 8
// baseline (speedup 1.0000x reference)
#include <cuda_runtime.h>
#include <cstdint>

#define B_ 4
#define C_ 3
#define H_ 360
#define W_ 640
#define HP 364
#define WP 644
#define GH 52
#define GW 92
#define BP (B_*GH*GW)   /* 19136 patches */
#define FH 64           /* F_HEAD */
#define FC 32           /* F_CH  */
#define NF 64           /* N_FEATS */

// ---------------- scratch (device globals; no allocation allowed) ----------
__device__ __align__(16) float g_feat1[BP*FH*25];   // conv1 out: [p][pos25][ic64]
__device__ __align__(16) float g_feat2[BP*FH*9];    // conv2 out: [p][oc*9+pos]
__device__ __align__(16) float g_kern [BP*FC*27];   // per-patch kernels [p][864]
__device__ __align__(16) float g_bias [BP*FC];      // per-patch bias [p][32]
__device__ __align__(16) float g_ymid [B_*FC*HP*WP];     // adaptive conv out
__device__ __align__(16) float g_y3  [(size_t)B_*NF*HP*WP]; // conv3 out
__device__ __align__(16) uint32_t g_wt [25*FC*NF];  // conv3 w tf32 [tap][ic][oc]
__device__ __align__(16) uint32_t g_wt2[9*FH*FH];   // conv2 w tf32 [tap][ic][oc]
__device__ __align__(16) uint32_t g_wt4[9*NF*16];   // conv4 w tf32 [tap][ic][oc16]

__device__ __forceinline__ float rgb_mean(int c) {
    return (c == 0) ? 0.4488f*255.0f : (c == 1) ? 0.4371f*255.0f : 0.404f*255.0f;
}

__device__ __forceinline__ uint32_t tf32_bits(float f) {
    uint32_t u;
    asm("cvt.rna.tf32.f32 %0, %1;" : "=r"(u) : "f"(f));
    return u;
}

#define MMA_TF32(ACC, A0,A1,A2,A3, B0,B1) \
    asm volatile("mma.sync.aligned.m16n8k8.row.col.f32.tf32.tf32.f32 " \
        "{%0,%1,%2,%3}, {%4,%5,%6,%7}, {%8,%9}, {%0,%1,%2,%3};\n" \
        : "+f"((ACC)[0]), "+f"((ACC)[1]), "+f"((ACC)[2]), "+f"((ACC)[3]) \
        : "r"(A0), "r"(A1), "r"(A2), "r"(A3), "r"(B0), "r"(B1))

// ---------------- weight transposes (tf32 pre-conversion) ----------------
__global__ void k5w_transpose(const float* __restrict__ w3) {
    int i = blockIdx.x*256 + threadIdx.x;
    if (i >= 25*FC*NF) return;
    int tap = i / (FC*NF);
    int rem = i - tap*(FC*NF);
    int ic = rem >> 6, oc = rem & 63;
    g_wt[i] = tf32_bits(w3[(oc*FC + ic)*25 + tap]);
}
__global__ void k2w_transpose(const float* __restrict__ w2) {
    int i = blockIdx.x*256 + threadIdx.x;
    if (i >= 9*FH*FH) return;
    int tap = i / (FH*FH);
    int rem = i - tap*(FH*FH);
    int ic = rem >> 6, oc = rem & 63;
    g_wt2[i] = tf32_bits(w2[(oc*FH + ic)*9 + tap]);
}
__global__ void k6w_transpose(const float* __restrict__ w4) {
    int i = blockIdx.x*256 + threadIdx.x;
    if (i >= 9*NF*16) return;
    int tap = i / (NF*16);
    int rem = i - tap*(NF*16);
    int ic = rem >> 4, oc = rem & 15;
    float v = (oc < 12) ? w4[(oc*NF + ic)*9 + tap] : 0.f;
    g_wt4[i] = tf32_bits(v);
}

// ---------------- K1: patch extract + conv1 3x3 VALID + relu (fp32).
// 128 thr = 4 patches x 1 warp. Thread = 2 oc (lane, lane+32), weights in 54
// regs; taps are warp-broadcast LDS (1 LDS per 2 FFMA).
__global__ void __launch_bounds__(128) k1_conv1(const float* __restrict__ x,
                                                const float* __restrict__ w1,
                                                const float* __restrict__ b1) {
    __shared__ float sp[4][148];
    __shared__ float ws[FH*27];
    __shared__ float bs[FH];
    int p0 = blockIdx.x*4;
    int tid = threadIdx.x;
    int pl = tid >> 5, lane = tid & 31;
    for (int i = tid; i < FH*27; i += 128) ws[i] = w1[i];
    if (tid < FH) bs[tid] = b1[tid];
    for (int i = tid; i < 4*147; i += 128) {
        int pp = i / 147, q = i - pp*147;
        int c = q/49, rr = q%49, ii = rr/7, jj = rr%7;
        int p = p0 + pp;
        int b = p/(GH*GW); int r = p%(GH*GW); int gi = r/GW, gj = r%GW;
        int h = gi*7 + ii, w = gj*7 + jj;
        float v = 0.f;
        if (h < H_ && w < W_) v = x[((b*C_+c)*H_ + h)*W_ + w] - rgb_mean(c);
        sp[pp][q] = v;
    }
    __syncthreads();
    float wr0[27], wr1[27];
    #pragma unroll
    for (int k = 0; k < 27; k++) { wr0[k] = ws[lane*27+k]; wr1[k] = ws[(lane+32)*27+k]; }
    float bv0 = bs[lane], bv1 = bs[lane+32];
    float* dst = &g_feat1[(size_t)(p0+pl)*1600];
    #pragma unroll
    for (int q = 0; q < 25; q++) {
        int oy = q/5, ox = q%5;
        float a0 = bv0, a1 = bv1;
        #pragma unroll
        for (int c = 0; c < 3; c++)
            #pragma unroll
            for (int ky = 0; ky < 3; ky++)
                #pragma unroll
                for (int kx = 0; kx < 3; kx++) {
                    float tap = sp[pl][c*49 + (oy+ky)*7 + (ox+kx)];
                    int k = c*9 + ky*3 + kx;
                    a0 += tap*wr0[k];
                    a1 += tap*wr1[k];
                }
        dst[q*64 + lane]      = fmaxf(a0, 0.f);
        dst[q*64 + lane + 32] = fmaxf(a1, 0.f);
    }
}

// ---------------- K2: conv2 3x3 VALID (64->64) + relu — tf32 mma.
// Warp-private weight staging (each warp stages the 16-oc slice it reads):
// no cross-warp syncs in the tap loop.
__global__ void __launch_bounds__(128) k2_conv2(const float* __restrict__ b2) {
    __shared__ __align__(16) uint32_t sf[4*25*68];    // [pl*25+pos][ic pad 68]
    __shared__ __align__(16) uint32_t wslab[64*72];   // [ic][oc pad 72]
    int tid = threadIdx.x;
    int p0 = blockIdx.x*4;
    int warp = tid >> 5, lane = tid & 31;
    int g = lane >> 2, t = lane & 3;

    for (int i = tid; i < 4*400; i += 128) {
        int pl = i / 400, rem = i - pl*400;
        int pos = rem >> 4, c = rem & 15;
        float4 v = *(const float4*)&g_feat1[(size_t)(p0+pl)*1600 + pos*64 + 4*c];
        uint32_t* dst = &sf[(pl*25+pos)*68 + 4*c];
        dst[0]=tf32_bits(v.x); dst[1]=tf32_bits(v.y);
        dst[2]=tf32_bits(v.z); dst[3]=tf32_bits(v.w);
    }
    __syncthreads();   // sf ready (only block-wide sync)

    int rB[5];
    #pragma unroll
    for (int j = 0; j < 5; j++) {
        int col = 8*j + g;
        int cc = (col < 36) ? col : 35;
        int pl = cc/9, pos = cc - pl*9;
        int oy = pos/3, ox = pos - oy*3;
        rB[j] = pl*25 + oy*5 + ox;
    }
    float acc[5][4];
    #pragma unroll
    for (int j = 0; j < 5; j++)
        #pragma unroll
        for (int q = 0; q < 4; q++) acc[j][q] = 0.f;

    for (int tap = 0; tap < 9; tap++) {
        __syncwarp();   // WAR: own warp done reading its slice
        #pragma unroll
        for (int u = lane; u < 256; u += 32) {   // 64 ic x 4 uint4 (16 oc)
            int ic = u >> 2, c = u & 3;
            *(uint4*)&wslab[ic*72 + 16*warp + 4*c] =
                *(const uint4*)&g_wt2[tap*4096 + ic*64 + 16*warp + 4*c];
        }
        __syncwarp();
        int dtr = tap/3, dtc = tap - dtr*3;
        int roff = (dtr*5 + dtc)*68;
        #pragma unroll
        for (int ks = 0; ks < 8; ks++) {
            int kl = ks*8;
            uint32_t a0 = wslab[(kl+t)*72   + 16*warp + g];
            uint32_t a1 = wslab[(kl+t)*72   + 16*warp + g + 8];
            uint32_t a2 = wslab[(kl+t+4)*72 + 16*warp + g];
            uint32_t a3 = wslab[(kl+t+4)*72 + 16*warp + g + 8];
            #pragma unroll
            for (int j = 0; j < 5; j++) {
                const uint32_t* bp = &sf[rB[j]*68 + roff + kl + t];
                uint32_t b0 = bp[0], b1 = bp[4];
                MMA_TF32(acc[j], a0,a1,a2,a3, b0,b1);
            }
        }
    }

    int oc0 = 16*warp + g;
    float bv0 = b2[oc0], bv1 = b2[oc0+8];
    #pragma unroll
    for (int j = 0; j < 5; j++) {
        #pragma unroll
        for (int h2 = 0; h2 < 2; h2++) {
            int col = 8*j + 2*t + h2;
            if (col >= 36) continue;
            int pl = col/9, pos = col - pl*9;
            float* d = g_feat2 + (size_t)(p0+pl)*576;
            d[oc0*9 + pos]     = fmaxf(acc[j][h2]   + bv0, 0.f);
            d[(oc0+8)*9 + pos] = fmaxf(acc[j][2+h2] + bv1, 0.f);
        }
    }
}

// ---------------- K3: fused GEMM C[BP][896] = feat2[BP][576] x [wk;wb]^T + [bk;bb]
// As warp-slice-staged (warp stages the 32 m-rows it reads, syncwarp only);
// Bs double-buffered: one __syncthreads per k-chunk instead of two.
__global__ void __launch_bounds__(128) k3_gemm(const float* __restrict__ wk,
                                               const float* __restrict__ bk,
                                               const float* __restrict__ wb,
                                               const float* __restrict__ bb) {
    __shared__ __align__(16) uint32_t As[128*36];
    __shared__ __align__(16) uint32_t Bs[2][64*36];
    int tid = threadIdx.x;
    int warp = tid >> 5, lane = tid & 31;
    int g = lane >> 2, t = lane & 3;
    int m0 = blockIdx.y*128, n0 = blockIdx.x*64;

    // staging helpers (inline lambdas)
    auto stageA = [&](int k0) {
        #pragma unroll
        for (int u = lane; u < 256; u += 32) {   // 32 rows x 8 float4
            int rl = u >> 3, c = u & 7;
            int rr = 32*warp + rl;
            int m = m0 + rr;
            float4 v = make_float4(0.f,0.f,0.f,0.f);
            if (m < BP) v = *(const float4*)&g_feat2[(size_t)m*576 + k0 + 4*c];
            uint32_t* dst = &As[rr*36 + 4*c];
            dst[0]=tf32_bits(v.x); dst[1]=tf32_bits(v.y);
            dst[2]=tf32_bits(v.z); dst[3]=tf32_bits(v.w);
        }
    };
    auto stageB = [&](int k0, int buf) {
        #pragma unroll
        for (int u = tid; u < 512; u += 128) {   // 64 rows x 8 float4
            int rr = u >> 3, c = u & 7;
            int n = n0 + rr;
            const float* src = (n < 864) ? &wk[(size_t)n*576] : &wb[(size_t)(n-864)*576];
            float4 v = *(const float4*)&src[k0 + 4*c];
            uint32_t* dst = &Bs[buf][rr*36 + 4*c];
            dst[0]=tf32_bits(v.x); dst[1]=tf32_bits(v.y);
            dst[2]=tf32_bits(v.z); dst[3]=tf32_bits(v.w);
        }
    };

    float acc[2][8][4];
    #pragma unroll
    for (int mt = 0; mt < 2; mt++)
        #pragma unroll
        for (int j = 0; j < 8; j++)
            #pragma unroll
            for (int q = 0; q < 4; q++) acc[mt][j][q] = 0.f;

    stageB(0, 0);
    stageA(0);
    __syncthreads();

    for (int ki = 0; ki < 18; ki++) {
        int buf = ki & 1;
        #pragma unroll
        for (int ks = 0; ks < 4; ks++) {
            int kl = ks*8;
            uint32_t bf[8][2];
            #pragma unroll
            for (int j = 0; j < 8; j++) {
                bf[j][0] = Bs[buf][(8*j+g)*36 + kl + t];
                bf[j][1] = Bs[buf][(8*j+g)*36 + kl + t + 4];
            }
            #pragma unroll
            for (int mt = 0; mt < 2; mt++) {
                int mb = 32*warp + 16*mt;
                uint32_t a0 = As[(mb+g)*36   + kl + t];
                uint32_t a1 = As[(mb+g+8)*36 + kl + t];
                uint32_t a2 = As[(mb+g)*36   + kl + t + 4];
                uint32_t a3 = As[(mb+g+8)*36 + kl + t + 4];
                #pragma unroll
                for (int j = 0; j < 8; j++)
                    MMA_TF32(acc[mt][j], a0,a1,a2,a3, bf[j][0], bf[j][1]);
            }
        }
        if (ki < 17) {
            int k0n = (ki+1)*32;
            __syncwarp();              // own warp done reading As
            stageA(k0n);
            stageB(k0n, buf ^ 1);
            __syncthreads();           // Bs[next] ready for all
        }
    }

    #pragma unroll
    for (int mt = 0; mt < 2; mt++) {
        int m = m0 + 32*warp + 16*mt + g;
        #pragma unroll
        for (int j = 0; j < 8; j++) {
            #pragma unroll
            for (int h2 = 0; h2 < 2; h2++) {
                int n = n0 + 8*j + 2*t + h2;
                float v0 = acc[mt][j][h2], v1 = acc[mt][j][2+h2];
                if (n < 864) {
                    float bv = bk[n];
                    if (m < BP)     g_kern[(size_t)m*864 + n]     = v0 + bv;
                    if (m+8 < BP)   g_kern[(size_t)(m+8)*864 + n] = v1 + bv;
                } else {
                    float bv = bb[n-864];
                    if (m < BP)     g_bias[(size_t)m*32 + (n-864)]     = v0 + bv;
                    if (m+8 < BP)   g_bias[(size_t)(m+8)*32 + (n-864)] = v1 + bv;
                }
            }
        }
    }
}

// ---------------- K4: adaptive per-patch 3x3 conv — 2 patches/block (98/128
// lanes active in compute vs 49/128 before).
__global__ void __launch_bounds__(128) k4_adapt(const float* __restrict__ x) {
    __shared__ float ks[2][FC*27];
    __shared__ float bsm[2][FC];
    __shared__ float xs[2][C_*81];
    int p0 = blockIdx.x*2;
    int tid = threadIdx.x;
    for (int i = tid; i < 2*FC*27; i += 128) {
        int pp = i / (FC*27), k = i % (FC*27);
        ks[pp][k] = g_kern[(size_t)(p0+pp)*(FC*27) + k];
    }
    if (tid < 2*FC) bsm[tid>>5][tid&31] = g_bias[(size_t)(p0+(tid>>5))*FC + (tid&31)];
    for (int i = tid; i < 2*C_*81; i += 128) xs[i/243][i%243] = 0.f;
    __syncthreads();
    for (int i = tid; i < 2*C_*49; i += 128) {
        int pp = i/147, q = i%147;
        int c = q/49, rr = q%49, ii = rr/7, jj = rr%7;
        int p = p0 + pp;
        int b = p/(GH*GW); int r = p%(GH*GW); int gi = r/GW, gj = r%GW;
        int h = gi*7+ii, w = gj*7+jj;
        float v = 0.f;
        if (h < H_ && w < W_) v = x[((b*C_+c)*H_+h)*W_+w] - rgb_mean(c);
        xs[pp][c*81 + (ii+1)*9 + (jj+1)] = v;
    }
    __syncthreads();
    if (tid < 98) {
        int pl = tid/49, q = tid - pl*49;
        int i = q/7, j = q%7;
        float v[27];
        #pragma unroll
        for (int c = 0; c < 3; c++)
            #pragma unroll
            for (int di = 0; di < 3; di++)
                #pragma unroll
                for (int dj = 0; dj < 3; dj++)
                    v[c*9+di*3+dj] = xs[pl][c*81 + (i+di)*9 + (j+dj)];
        int p = p0 + pl;
        int b = p/(GH*GW); int r = p%(GH*GW); int gi = r/GW, gj = r%GW;
        int h = gi*7+i, w = gj*7+j;
        for (int f = 0; f < FC; f++) {
            float acc = bsm[pl][f];
            #pragma unroll
            for (int k = 0; k < 27; k++) acc += ks[pl][f*27+k]*v[k];
            g_ymid[((b*FC+f)*HP + h)*WP + w] = acc;
        }
    }
}

// ---------------- K5: conv3 5x5 pad2, 32->64, relu — tf32 mma, warp-private
// weight staging: single block-wide sync, tap loop uses __syncwarp only.
__global__ void __launch_bounds__(128) k5_conv3(const float* __restrict__ b3) {
    __shared__ __align__(16) uint32_t tileS[12*20*36];
    __shared__ __align__(16) uint32_t wslab[32*72];
    __shared__ float sbias[NF];
    int b  = blockIdx.z;
    int by = blockIdx.y, bx = blockIdx.x;
    int tid = threadIdx.x;
    int warp = tid >> 5, lane = tid & 31;
    int g = lane >> 2, t = lane & 3;
    int gh0 = by*8 - 2, gw0 = bx*16 - 2;

    for (int i = tid; i < FC*240; i += 128) {
        int ic = i / 240, pos = i - ic*240;
        int r = pos / 20, c = pos - r*20;
        int hh = gh0 + r, ww = gw0 + c;
        float v = 0.f;
        if (hh >= 0 && hh < HP && ww >= 0 && ww < WP)
            v = g_ymid[((b*FC + ic)*HP + hh)*WP + ww];
        tileS[(r*20 + c)*36 + ic] = tf32_bits(v);
    }
    if (tid < NF) sbias[tid] = b3[tid];
    __syncthreads();   // tileS + sbias ready (only block-wide sync)

    float acc[16][4];
    #pragma unroll
    for (int j = 0; j < 16; j++)
        #pragma unroll
        for (int q = 0; q < 4; q++) acc[j][q] = 0.f;

    for (int tap = 0; tap < 25; tap++) {
        __syncwarp();
        #pragma unroll
        for (int u = lane; u < 128; u += 32) {   // 32 ic x 4 uint4 (own 16 oc)
            int ic = u >> 2, c = u & 3;
            *(uint4*)&wslab[ic*72 + 16*warp + 4*c] =
                *(const uint4*)&g_wt[tap*2048 + ic*64 + 16*warp + 4*c];
        }
        __syncwarp();
        int dtr = tap / 5, dtc = tap - dtr*5;
        #pragma unroll
        for (int ks = 0; ks < 4; ks++) {
            int ic0 = ks*8;
            uint32_t a0 = wslab[(ic0+t)*72   + 16*warp + g];
            uint32_t a1 = wslab[(ic0+t)*72   + 16*warp + g + 8];
            uint32_t a2 = wslab[(ic0+t+4)*72 + 16*warp + g];
            uint32_t a3 = wslab[(ic0+t+4)*72 + 16*warp + g + 8];
            #pragma unroll
            for (int j = 0; j < 16; j++) {
                int jr = j >> 1, jc = (j & 1)*8;
                const uint32_t* bp = &tileS[((jr+dtr)*20 + jc + g + dtc)*36 + ic0 + t];
                uint32_t b0 = bp[0], b1 = bp[4];
                MMA_TF32(acc[j], a0,a1,a2,a3, b0,b1);
            }
        }
    }

    int oc0 = 16*warp + g;
    float bv0 = sbias[oc0], bv1 = sbias[oc0 + 8];
    #pragma unroll
    for (int j = 0; j < 16; j++) {
        int jr = j >> 1, jc = (j & 1)*8;
        int py = by*8 + jr;
        if (py >= HP) continue;
        int px = bx*16 + jc + 2*t;
        float* base0 = g_y3 + (((size_t)b*NF + oc0)*HP + py)*WP;
        float* base1 = g_y3 + (((size_t)b*NF + oc0 + 8)*HP + py)*WP;
        if (px < WP) {
            base0[px] = fmaxf(acc[j][0] + bv0, 0.f);
            base1[px] = fmaxf(acc[j][2] + bv1, 0.f);
        }
        if (px + 1 < WP) {
            base0[px+1] = fmaxf(acc[j][1] + bv0, 0.f);
            base1[px+1] = fmaxf(acc[j][3] + bv1, 0.f);
        }
    }
}

// ---------------- K6: conv4 3x3 pad1 (64->12) + pixel-shuffle — tf32 mma.
// Per-warp weight replicas (all warps need the same 16-oc slab): tap loop is
// sync-free; only tile (re)staging uses block syncs (4 total).
__global__ void __launch_bounds__(128) k6_conv4(const float* __restrict__ b4,
                                                float* __restrict__ out) {
    __shared__ __align__(16) uint32_t tileS[180*36];     // 25.9 KB
    __shared__ __align__(16) uint32_t wpriv[4*32*24];    // 12.3 KB (per-warp)
    __shared__ float sbias[16];
    int b  = blockIdx.z;
    int by = blockIdx.y, bx = blockIdx.x;
    int tid = threadIdx.x;
    int warp = tid >> 5, lane = tid & 31;
    int g = lane >> 2, t = lane & 3;
    int gh0 = by*8 - 1, gw0 = bx*16 - 1;
    if (tid < 16) sbias[tid] = (tid < 12) ? b4[tid] : 0.f;

    float acc[4][4];
    #pragma unroll
    for (int j = 0; j < 4; j++)
        #pragma unroll
        for (int q = 0; q < 4; q++) acc[j][q] = 0.f;

    for (int half = 0; half < 2; half++) {
        int icg = half*32;
        __syncthreads();   // WAR on tileS (also covers sbias on first iter)
        for (int i = tid; i < 32*180; i += 128) {
            int icl = i / 180, pos = i - icl*180;
            int r = pos / 18, c = pos - r*18;
            int hh = gh0 + r, ww = gw0 + c;
            float v = 0.f;
            if (hh >= 0 && ww >= 0)
                v = g_y3[(((size_t)b*NF + icg + icl)*HP + hh)*WP + ww];
            tileS[pos*36 + icl] = tf32_bits(v);
        }
        __syncthreads();
        for (int tap = 0; tap < 9; tap++) {
            __syncwarp();
            #pragma unroll
            for (int u = lane; u < 128; u += 32) {   // 32 ic x 4 uint4
                int icl = u >> 2, c = u & 3;
                *(uint4*)&wpriv[warp*768 + icl*24 + 4*c] =
                    *(const uint4*)&g_wt4[tap*(NF*16) + (icg+icl)*16 + 4*c];
            }
            __syncwarp();
            int dtr = tap/3, dtc = tap - dtr*3;
            #pragma unroll
            for (int ks = 0; ks < 4; ks++) {
                int kl = ks*8;
                uint32_t a0 = wpriv[warp*768 + (kl+t)*24   + g];
                uint32_t a1 = wpriv[warp*768 + (kl+t)*24   + g + 8];
                uint32_t a2 = wpriv[warp*768 + (kl+t+4)*24 + g];
                uint32_t a3 = wpriv[warp*768 + (kl+t+4)*24 + g + 8];
                #pragma unroll
                for (int jj = 0; jj < 4; jj++) {
                    int jn = warp*4 + jj;
                    int jr = jn >> 1, jc = (jn & 1)*8;
                    const uint32_t* bp = &tileS[((jr+dtr)*18 + jc + g + dtc)*36 + kl + t];
                    uint32_t b0 = bp[0], b1 = bp[4];
                    MMA_TF32(acc[jj], a0,a1,a2,a3, b0,b1);
                }
            }
        }
    }

    #pragma unroll
    for (int jj = 0; jj < 4; jj++) {
        int jn = warp*4 + jj;
        int jr = jn >> 1, jc = (jn & 1)*8;
        int h = by*8 + jr;            // < 360
        int px = bx*16 + jc + 2*t;    // < 640
        #pragma unroll
        for (int mrow = 0; mrow < 2; mrow++) {
            int o = g + 8*mrow;
            if (o >= 12) continue;
            int co = o >> 2, s1 = (o >> 1) & 1, s2 = o & 1;
            float bv = sbias[o] + rgb_mean(co);
            float* dst = out + ((b*3+co)*720 + 2*h + s1)*1280;
            dst[2*px + s2]     = acc[jj][2*mrow]   + bv;
            dst[2*(px+1) + s2] = acc[jj][2*mrow+1] + bv;
        }
    }
}

// ---------------- launch ----------------
extern "C" void kernel_launch(void* const* d_in, const int* in_sizes, int n_in,
                              void* d_out, int out_size) {
    const float* x  = (const float*)d_in[0];
    const float* w1 = (const float*)d_in[1];
    const float* b1 = (const float*)d_in[2];
    const float* w2 = (const float*)d_in[3];
    const float* b2 = (const float*)d_in[4];
    const float* wk = (const float*)d_in[5];
    const float* bk = (const float*)d_in[6];
    const float* wb = (const float*)d_in[7];
    const float* bb = (const float*)d_in[8];
    const float* w3 = (const float*)d_in[9];
    const float* b3 = (const float*)d_in[10];
    const float* w4 = (const float*)d_in[11];
    const float* b4 = (const float*)d_in[12];
    float* out = (float*)d_out;

    k5w_transpose<<<(25*FC*NF + 255)/256, 256>>>(w3);
    k2w_transpose<<<(9*FH*FH + 255)/256, 256>>>(w2);
    k6w_transpose<<<(9*NF*16 + 255)/256, 256>>>(w4);
    k1_conv1<<<BP/4, 128>>>(x, w1, b1);
    k2_conv2<<<BP/4, 128>>>(b2);
    k3_gemm<<<dim3(14, (BP+127)/128), 128>>>(wk, bk, wb, bb);
    k4_adapt<<<BP/2, 128>>>(x);
    k5_conv3<<<dim3((WP+15)/16, (HP+7)/8, B_), 128>>>(b3);
    k6_conv4<<<dim3(W_/16, H_/8, B_), 128>>>(b4, out);
}

// round 9
// speedup vs baseline: 1.0869x; 1.0869x over previous
#include <cuda_runtime.h>
#include <cstdint>

#define B_ 4
#define C_ 3
#define H_ 360
#define W_ 640
#define HP 364
#define WP 644
#define GH 52
#define GW 92
#define BP (B_*GH*GW)   /* 19136 patches */
#define FH 64           /* F_HEAD */
#define FC 32           /* F_CH  */
#define NF 64           /* N_FEATS */

// ---------------- scratch (device globals; no allocation allowed) ----------
__device__ __align__(16) float g_feat1[BP*FH*25];   // conv1 out: [p][pos25][ic64]
__device__ __align__(16) float g_feat2[BP*FH*9];    // conv2 out: [p][oc*9+pos]
__device__ __align__(16) float g_kern [BP*FC*27];   // per-patch kernels [p][864]
__device__ __align__(16) float g_bias [BP*FC];      // per-patch bias [p][32]
__device__ __align__(16) float g_ymid [B_*FC*HP*WP];     // adaptive conv out
__device__ __align__(16) float g_y3  [(size_t)B_*NF*HP*WP]; // conv3 out
__device__ __align__(16) uint32_t g_wt [25*FC*NF];  // conv3 w tf32 [tap][ic][oc]
__device__ __align__(16) uint32_t g_wt2[9*FH*FH];   // conv2 w tf32 [tap][ic][oc]
__device__ __align__(16) uint32_t g_wt4[9*NF*16];   // conv4 w tf32 [tap][ic][oc16]

__device__ __forceinline__ float rgb_mean(int c) {
    return (c == 0) ? 0.4488f*255.0f : (c == 1) ? 0.4371f*255.0f : 0.404f*255.0f;
}

__device__ __forceinline__ uint32_t tf32_bits(float f) {
    uint32_t u;
    asm("cvt.rna.tf32.f32 %0, %1;" : "=r"(u) : "f"(f));
    return u;
}

#define MMA_TF32(ACC, A0,A1,A2,A3, B0,B1) \
    asm volatile("mma.sync.aligned.m16n8k8.row.col.f32.tf32.tf32.f32 " \
        "{%0,%1,%2,%3}, {%4,%5,%6,%7}, {%8,%9}, {%0,%1,%2,%3};\n" \
        : "+f"((ACC)[0]), "+f"((ACC)[1]), "+f"((ACC)[2]), "+f"((ACC)[3]) \
        : "r"(A0), "r"(A1), "r"(A2), "r"(A3), "r"(B0), "r"(B1))

// ---------------- weight transposes (tf32 pre-conversion) ----------------
__global__ void k5w_transpose(const float* __restrict__ w3) {
    int i = blockIdx.x*256 + threadIdx.x;
    if (i >= 25*FC*NF) return;
    int tap = i / (FC*NF);
    int rem = i - tap*(FC*NF);
    int ic = rem >> 6, oc = rem & 63;
    g_wt[i] = tf32_bits(w3[(oc*FC + ic)*25 + tap]);
}
__global__ void k2w_transpose(const float* __restrict__ w2) {
    int i = blockIdx.x*256 + threadIdx.x;
    if (i >= 9*FH*FH) return;
    int tap = i / (FH*FH);
    int rem = i - tap*(FH*FH);
    int ic = rem >> 6, oc = rem & 63;
    g_wt2[i] = tf32_bits(w2[(oc*FH + ic)*9 + tap]);
}
__global__ void k6w_transpose(const float* __restrict__ w4) {
    int i = blockIdx.x*256 + threadIdx.x;
    if (i >= 9*NF*16) return;
    int tap = i / (NF*16);
    int rem = i - tap*(NF*16);
    int ic = rem >> 4, oc = rem & 15;
    float v = (oc < 12) ? w4[(oc*NF + ic)*9 + tap] : 0.f;
    g_wt4[i] = tf32_bits(v);
}

// ---------------- K1: patch extract + conv1 3x3 VALID + relu (fp32).
// 128 thr = 4 patches x 1 warp. Thread = 2 oc (lane, lane+32), weights in 54
// regs; taps are warp-broadcast LDS (1 LDS per 2 FFMA). [R8 verified: -130us]
__global__ void __launch_bounds__(128) k1_conv1(const float* __restrict__ x,
                                                const float* __restrict__ w1,
                                                const float* __restrict__ b1) {
    __shared__ float sp[4][148];
    __shared__ float ws[FH*27];
    __shared__ float bs[FH];
    int p0 = blockIdx.x*4;
    int tid = threadIdx.x;
    int pl = tid >> 5, lane = tid & 31;
    for (int i = tid; i < FH*27; i += 128) ws[i] = w1[i];
    if (tid < FH) bs[tid] = b1[tid];
    for (int i = tid; i < 4*147; i += 128) {
        int pp = i / 147, q = i - pp*147;
        int c = q/49, rr = q%49, ii = rr/7, jj = rr%7;
        int p = p0 + pp;
        int b = p/(GH*GW); int r = p%(GH*GW); int gi = r/GW, gj = r%GW;
        int h = gi*7 + ii, w = gj*7 + jj;
        float v = 0.f;
        if (h < H_ && w < W_) v = x[((b*C_+c)*H_ + h)*W_ + w] - rgb_mean(c);
        sp[pp][q] = v;
    }
    __syncthreads();
    float wr0[27], wr1[27];
    #pragma unroll
    for (int k = 0; k < 27; k++) { wr0[k] = ws[lane*27+k]; wr1[k] = ws[(lane+32)*27+k]; }
    float bv0 = bs[lane], bv1 = bs[lane+32];
    float* dst = &g_feat1[(size_t)(p0+pl)*1600];
    #pragma unroll
    for (int q = 0; q < 25; q++) {
        int oy = q/5, ox = q%5;
        float a0 = bv0, a1 = bv1;
        #pragma unroll
        for (int c = 0; c < 3; c++)
            #pragma unroll
            for (int ky = 0; ky < 3; ky++)
                #pragma unroll
                for (int kx = 0; kx < 3; kx++) {
                    float tap = sp[pl][c*49 + (oy+ky)*7 + (ox+kx)];
                    int k = c*9 + ky*3 + kx;
                    a0 += tap*wr0[k];
                    a1 += tap*wr1[k];
                }
        dst[q*64 + lane]      = fmaxf(a0, 0.f);
        dst[q*64 + lane + 32] = fmaxf(a1, 0.f);
    }
}

// ---------------- K2: conv2 3x3 VALID (64->64) + relu — tf32 mma (R7 version:
// cooperative block-wide weight staging; warp-private variant regressed).
__global__ void __launch_bounds__(128) k2_conv2(const float* __restrict__ b2) {
    __shared__ __align__(16) uint32_t sf[4*25*68];    // [pl*25+pos][ic pad 68]
    __shared__ __align__(16) uint32_t wslab[64*72];   // [ic][oc pad 72]
    int tid = threadIdx.x;
    int p0 = blockIdx.x*4;
    int warp = tid >> 5, lane = tid & 31;
    int g = lane >> 2, t = lane & 3;

    for (int i = tid; i < 4*400; i += 128) {
        int pl = i / 400, rem = i - pl*400;
        int pos = rem >> 4, c = rem & 15;
        float4 v = *(const float4*)&g_feat1[(size_t)(p0+pl)*1600 + pos*64 + 4*c];
        uint32_t* dst = &sf[(pl*25+pos)*68 + 4*c];
        dst[0]=tf32_bits(v.x); dst[1]=tf32_bits(v.y);
        dst[2]=tf32_bits(v.z); dst[3]=tf32_bits(v.w);
    }

    int rB[5];
    #pragma unroll
    for (int j = 0; j < 5; j++) {
        int col = 8*j + g;
        int cc = (col < 36) ? col : 35;
        int pl = cc/9, pos = cc - pl*9;
        int oy = pos/3, ox = pos - oy*3;
        rB[j] = pl*25 + oy*5 + ox;
    }
    float acc[5][4];
    #pragma unroll
    for (int j = 0; j < 5; j++)
        #pragma unroll
        for (int q = 0; q < 4; q++) acc[j][q] = 0.f;

    for (int tap = 0; tap < 9; tap++) {
        __syncthreads();
        #pragma unroll
        for (int i = tid; i < 1024; i += 128) {   // uint4 copy, preconverted
            int ic = i >> 4, c = i & 15;
            *(uint4*)&wslab[ic*72 + 4*c] = *(const uint4*)&g_wt2[tap*4096 + ic*64 + 4*c];
        }
        __syncthreads();
        int dtr = tap/3, dtc = tap - dtr*3;
        int roff = (dtr*5 + dtc)*68;
        #pragma unroll
        for (int ks = 0; ks < 8; ks++) {
            int kl = ks*8;
            uint32_t a0 = wslab[(kl+t)*72   + 16*warp + g];
            uint32_t a1 = wslab[(kl+t)*72   + 16*warp + g + 8];
            uint32_t a2 = wslab[(kl+t+4)*72 + 16*warp + g];
            uint32_t a3 = wslab[(kl+t+4)*72 + 16*warp + g + 8];
            #pragma unroll
            for (int j = 0; j < 5; j++) {
                const uint32_t* bp = &sf[rB[j]*68 + roff + kl + t];
                uint32_t b0 = bp[0], b1 = bp[4];
                MMA_TF32(acc[j], a0,a1,a2,a3, b0,b1);
            }
        }
    }

    int oc0 = 16*warp + g;
    float bv0 = b2[oc0], bv1 = b2[oc0+8];
    #pragma unroll
    for (int j = 0; j < 5; j++) {
        #pragma unroll
        for (int h2 = 0; h2 < 2; h2++) {
            int col = 8*j + 2*t + h2;
            if (col >= 36) continue;
            int pl = col/9, pos = col - pl*9;
            float* d = g_feat2 + (size_t)(p0+pl)*576;
            d[oc0*9 + pos]     = fmaxf(acc[j][h2]   + bv0, 0.f);
            d[(oc0+8)*9 + pos] = fmaxf(acc[j][2+h2] + bv1, 0.f);
        }
    }
}

// ---------------- K3: fused GEMM C[BP][896] = feat2[BP][576] x [wk;wb]^T + [bk;bb]
// (R7 version: single-buffered, two syncs per chunk — double-buffer regressed.)
__global__ void __launch_bounds__(128) k3_gemm(const float* __restrict__ wk,
                                               const float* __restrict__ bk,
                                               const float* __restrict__ wb,
                                               const float* __restrict__ bb) {
    __shared__ uint32_t As[128*36];
    __shared__ uint32_t Bs[64*36];
    int tid = threadIdx.x;
    int warp = tid >> 5, lane = tid & 31;
    int g = lane >> 2, t = lane & 3;
    int m0 = blockIdx.y*128, n0 = blockIdx.x*64;
    int c = tid & 7, r0 = tid >> 3;

    float acc[2][8][4];
    #pragma unroll
    for (int mt = 0; mt < 2; mt++)
        #pragma unroll
        for (int j = 0; j < 8; j++)
            #pragma unroll
            for (int q = 0; q < 4; q++) acc[mt][j][q] = 0.f;

    for (int k0 = 0; k0 < 576; k0 += 32) {
        __syncthreads();
        #pragma unroll
        for (int rr = r0; rr < 128; rr += 16) {
            int m = m0 + rr;
            float4 v = make_float4(0.f,0.f,0.f,0.f);
            if (m < BP) v = *(const float4*)&g_feat2[(size_t)m*576 + k0 + 4*c];
            uint32_t* dst = &As[rr*36 + 4*c];
            dst[0]=tf32_bits(v.x); dst[1]=tf32_bits(v.y);
            dst[2]=tf32_bits(v.z); dst[3]=tf32_bits(v.w);
        }
        #pragma unroll
        for (int rr = r0; rr < 64; rr += 16) {
            int n = n0 + rr;
            const float* src = (n < 864) ? &wk[(size_t)n*576] : &wb[(size_t)(n-864)*576];
            float4 v = *(const float4*)&src[k0 + 4*c];
            uint32_t* dst = &Bs[rr*36 + 4*c];
            dst[0]=tf32_bits(v.x); dst[1]=tf32_bits(v.y);
            dst[2]=tf32_bits(v.z); dst[3]=tf32_bits(v.w);
        }
        __syncthreads();
        #pragma unroll
        for (int ks = 0; ks < 4; ks++) {
            int kl = ks*8;
            uint32_t bf[8][2];
            #pragma unroll
            for (int j = 0; j < 8; j++) {
                bf[j][0] = Bs[(8*j+g)*36 + kl + t];
                bf[j][1] = Bs[(8*j+g)*36 + kl + t + 4];
            }
            #pragma unroll
            for (int mt = 0; mt < 2; mt++) {
                int mb = 32*warp + 16*mt;
                uint32_t a0 = As[(mb+g)*36   + kl + t];
                uint32_t a1 = As[(mb+g+8)*36 + kl + t];
                uint32_t a2 = As[(mb+g)*36   + kl + t + 4];
                uint32_t a3 = As[(mb+g+8)*36 + kl + t + 4];
                #pragma unroll
                for (int j = 0; j < 8; j++)
                    MMA_TF32(acc[mt][j], a0,a1,a2,a3, bf[j][0], bf[j][1]);
            }
        }
    }

    #pragma unroll
    for (int mt = 0; mt < 2; mt++) {
        int m = m0 + 32*warp + 16*mt + g;
        #pragma unroll
        for (int j = 0; j < 8; j++) {
            #pragma unroll
            for (int h2 = 0; h2 < 2; h2++) {
                int n = n0 + 8*j + 2*t + h2;
                float v0 = acc[mt][j][h2], v1 = acc[mt][j][2+h2];
                if (n < 864) {
                    float bv = bk[n];
                    if (m < BP)     g_kern[(size_t)m*864 + n]     = v0 + bv;
                    if (m+8 < BP)   g_kern[(size_t)(m+8)*864 + n] = v1 + bv;
                } else {
                    float bv = bb[n-864];
                    if (m < BP)     g_bias[(size_t)m*32 + (n-864)]     = v0 + bv;
                    if (m+8 < BP)   g_bias[(size_t)(m+8)*32 + (n-864)] = v1 + bv;
                }
            }
        }
    }
}

// ---------------- K4: adaptive per-patch 3x3 conv — 2 patches/block
// (R8 version: 98/128 compute lanes).
__global__ void __launch_bounds__(128) k4_adapt(const float* __restrict__ x) {
    __shared__ float ks[2][FC*27];
    __shared__ float bsm[2][FC];
    __shared__ float xs[2][C_*81];
    int p0 = blockIdx.x*2;
    int tid = threadIdx.x;
    for (int i = tid; i < 2*FC*27; i += 128) {
        int pp = i / (FC*27), k = i % (FC*27);
        ks[pp][k] = g_kern[(size_t)(p0+pp)*(FC*27) + k];
    }
    if (tid < 2*FC) bsm[tid>>5][tid&31] = g_bias[(size_t)(p0+(tid>>5))*FC + (tid&31)];
    for (int i = tid; i < 2*C_*81; i += 128) xs[i/243][i%243] = 0.f;
    __syncthreads();
    for (int i = tid; i < 2*C_*49; i += 128) {
        int pp = i/147, q = i%147;
        int c = q/49, rr = q%49, ii = rr/7, jj = rr%7;
        int p = p0 + pp;
        int b = p/(GH*GW); int r = p%(GH*GW); int gi = r/GW, gj = r%GW;
        int h = gi*7+ii, w = gj*7+jj;
        float v = 0.f;
        if (h < H_ && w < W_) v = x[((b*C_+c)*H_+h)*W_+w] - rgb_mean(c);
        xs[pp][c*81 + (ii+1)*9 + (jj+1)] = v;
    }
    __syncthreads();
    if (tid < 98) {
        int pl = tid/49, q = tid - pl*49;
        int i = q/7, j = q%7;
        float v[27];
        #pragma unroll
        for (int c = 0; c < 3; c++)
            #pragma unroll
            for (int di = 0; di < 3; di++)
                #pragma unroll
                for (int dj = 0; dj < 3; dj++)
                    v[c*9+di*3+dj] = xs[pl][c*81 + (i+di)*9 + (j+dj)];
        int p = p0 + pl;
        int b = p/(GH*GW); int r = p%(GH*GW); int gi = r/GW, gj = r%GW;
        int h = gi*7+i, w = gj*7+j;
        for (int f = 0; f < FC; f++) {
            float acc = bsm[pl][f];
            #pragma unroll
            for (int k = 0; k < 27; k++) acc += ks[pl][f*27+k]*v[k];
            g_ymid[((b*FC+f)*HP + h)*WP + w] = acc;
        }
    }
}

// ---------------- K5: conv3 5x5 pad2, 32->64, relu — tf32 mma (R7 version).
__global__ void __launch_bounds__(128) k5_conv3(const float* __restrict__ b3) {
    __shared__ __align__(16) uint32_t tileS[12*20*36];
    __shared__ __align__(16) uint32_t wslab[32*72];
    __shared__ float sbias[NF];
    int b  = blockIdx.z;
    int by = blockIdx.y, bx = blockIdx.x;
    int tid = threadIdx.x;
    int warp = tid >> 5, lane = tid & 31;
    int g = lane >> 2, t = lane & 3;
    int gh0 = by*8 - 2, gw0 = bx*16 - 2;

    for (int i = tid; i < FC*240; i += 128) {
        int ic = i / 240, pos = i - ic*240;
        int r = pos / 20, c = pos - r*20;
        int hh = gh0 + r, ww = gw0 + c;
        float v = 0.f;
        if (hh >= 0 && hh < HP && ww >= 0 && ww < WP)
            v = g_ymid[((b*FC + ic)*HP + hh)*WP + ww];
        tileS[(r*20 + c)*36 + ic] = tf32_bits(v);
    }
    if (tid < NF) sbias[tid] = b3[tid];

    float acc[16][4];
    #pragma unroll
    for (int j = 0; j < 16; j++)
        #pragma unroll
        for (int q = 0; q < 4; q++) acc[j][q] = 0.f;

    for (int tap = 0; tap < 25; tap++) {
        __syncthreads();
        #pragma unroll
        for (int i = tid; i < 512; i += 128) {   // uint4 copy, preconverted
            int ic = i >> 4, c = i & 15;
            *(uint4*)&wslab[ic*72 + 4*c] = *(const uint4*)&g_wt[tap*2048 + ic*64 + 4*c];
        }
        __syncthreads();
        int dtr = tap / 5, dtc = tap - dtr*5;
        #pragma unroll
        for (int ks = 0; ks < 4; ks++) {
            int ic0 = ks*8;
            uint32_t a0 = wslab[(ic0+t)*72   + 16*warp + g];
            uint32_t a1 = wslab[(ic0+t)*72   + 16*warp + g + 8];
            uint32_t a2 = wslab[(ic0+t+4)*72 + 16*warp + g];
            uint32_t a3 = wslab[(ic0+t+4)*72 + 16*warp + g + 8];
            #pragma unroll
            for (int j = 0; j < 16; j++) {
                int jr = j >> 1, jc = (j & 1)*8;
                const uint32_t* bp = &tileS[((jr+dtr)*20 + jc + g + dtc)*36 + ic0 + t];
                uint32_t b0 = bp[0], b1 = bp[4];
                MMA_TF32(acc[j], a0,a1,a2,a3, b0,b1);
            }
        }
    }

    int oc0 = 16*warp + g;
    float bv0 = sbias[oc0], bv1 = sbias[oc0 + 8];
    #pragma unroll
    for (int j = 0; j < 16; j++) {
        int jr = j >> 1, jc = (j & 1)*8;
        int py = by*8 + jr;
        if (py >= HP) continue;
        int px = bx*16 + jc + 2*t;
        float* base0 = g_y3 + (((size_t)b*NF + oc0)*HP + py)*WP;
        float* base1 = g_y3 + (((size_t)b*NF + oc0 + 8)*HP + py)*WP;
        if (px < WP) {
            base0[px] = fmaxf(acc[j][0] + bv0, 0.f);
            base1[px] = fmaxf(acc[j][2] + bv1, 0.f);
        }
        if (px + 1 < WP) {
            base0[px+1] = fmaxf(acc[j][1] + bv0, 0.f);
            base1[px+1] = fmaxf(acc[j][3] + bv1, 0.f);
        }
    }
}

// ---------------- K6: conv4 3x3 pad1 (64->12) + pixel-shuffle — tf32 mma
// (R7 version: shared weight slab, block syncs).
__global__ void __launch_bounds__(128) k6_conv4(const float* __restrict__ b4,
                                                float* __restrict__ out) {
    __shared__ __align__(16) uint32_t tileS[180*36];   // 25.9 KB
    __shared__ __align__(16) uint32_t wslab[32*24];    //  3 KB
    __shared__ float sbias[16];
    int b  = blockIdx.z;
    int by = blockIdx.y, bx = blockIdx.x;
    int tid = threadIdx.x;
    int warp = tid >> 5, lane = tid & 31;
    int g = lane >> 2, t = lane & 3;
    int gh0 = by*8 - 1, gw0 = bx*16 - 1;
    if (tid < 16) sbias[tid] = (tid < 12) ? b4[tid] : 0.f;

    float acc[4][4];
    #pragma unroll
    for (int j = 0; j < 4; j++)
        #pragma unroll
        for (int q = 0; q < 4; q++) acc[j][q] = 0.f;

    for (int half = 0; half < 2; half++) {
        int icg = half*32;
        __syncthreads();   // WAR on tileS
        for (int i = tid; i < 32*180; i += 128) {
            int icl = i / 180, pos = i - icl*180;
            int r = pos / 18, c = pos - r*18;
            int hh = gh0 + r, ww = gw0 + c;
            float v = 0.f;
            if (hh >= 0 && ww >= 0)
                v = g_y3[(((size_t)b*NF + icg + icl)*HP + hh)*WP + ww];
            tileS[pos*36 + icl] = tf32_bits(v);
        }
        for (int tap = 0; tap < 9; tap++) {
            __syncthreads();   // WAR on wslab (first iter also covers tileS)
            {   // 512 uint32 = 128 uint4, one per thread
                int icl = tid >> 2, c = tid & 3;
                *(uint4*)&wslab[icl*24 + 4*c] =
                    *(const uint4*)&g_wt4[tap*(NF*16) + (icg+icl)*16 + 4*c];
            }
            __syncthreads();
            int dtr = tap/3, dtc = tap - dtr*3;
            #pragma unroll
            for (int ks = 0; ks < 4; ks++) {
                int kl = ks*8;
                uint32_t a0 = wslab[(kl+t)*24   + g];
                uint32_t a1 = wslab[(kl+t)*24   + g + 8];
                uint32_t a2 = wslab[(kl+t+4)*24 + g];
                uint32_t a3 = wslab[(kl+t+4)*24 + g + 8];
                #pragma unroll
                for (int jj = 0; jj < 4; jj++) {
                    int jn = warp*4 + jj;
                    int jr = jn >> 1, jc = (jn & 1)*8;
                    const uint32_t* bp = &tileS[((jr+dtr)*18 + jc + g + dtc)*36 + kl + t];
                    uint32_t b0 = bp[0], b1 = bp[4];
                    MMA_TF32(acc[jj], a0,a1,a2,a3, b0,b1);
                }
            }
        }
    }

    #pragma unroll
    for (int jj = 0; jj < 4; jj++) {
        int jn = warp*4 + jj;
        int jr = jn >> 1, jc = (jn & 1)*8;
        int h = by*8 + jr;            // < 360
        int px = bx*16 + jc + 2*t;    // < 640
        #pragma unroll
        for (int mrow = 0; mrow < 2; mrow++) {
            int o = g + 8*mrow;
            if (o >= 12) continue;
            int co = o >> 2, s1 = (o >> 1) & 1, s2 = o & 1;
            float bv = sbias[o] + rgb_mean(co);
            float* dst = out + ((b*3+co)*720 + 2*h + s1)*1280;
            dst[2*px + s2]     = acc[jj][2*mrow]   + bv;
            dst[2*(px+1) + s2] = acc[jj][2*mrow+1] + bv;
        }
    }
}

// ---------------- launch ----------------
extern "C" void kernel_launch(void* const* d_in, const int* in_sizes, int n_in,
                              void* d_out, int out_size) {
    const float* x  = (const float*)d_in[0];
    const float* w1 = (const float*)d_in[1];
    const float* b1 = (const float*)d_in[2];
    const float* w2 = (const float*)d_in[3];
    const float* b2 = (const float*)d_in[4];
    const float* wk = (const float*)d_in[5];
    const float* bk = (const float*)d_in[6];
    const float* wb = (const float*)d_in[7];
    const float* bb = (const float*)d_in[8];
    const float* w3 = (const float*)d_in[9];
    const float* b3 = (const float*)d_in[10];
    const float* w4 = (const float*)d_in[11];
    const float* b4 = (const float*)d_in[12];
    float* out = (float*)d_out;

    k5w_transpose<<<(25*FC*NF + 255)/256, 256>>>(w3);
    k2w_transpose<<<(9*FH*FH + 255)/256, 256>>>(w2);
    k6w_transpose<<<(9*NF*16 + 255)/256, 256>>>(w4);
    k1_conv1<<<BP/4, 128>>>(x, w1, b1);
    k2_conv2<<<BP/4, 128>>>(b2);
    k3_gemm<<<dim3(14, (BP+127)/128), 128>>>(wk, bk, wb, bb);
    k4_adapt<<<BP/2, 128>>>(x);
    k5_conv3<<<dim3((WP+15)/16, (HP+7)/8, B_), 128>>>(b3);
    k6_conv4<<<dim3(W_/16, H_/8, B_), 128>>>(b4, out);
}

// round 10
// speedup vs baseline: 1.1029x; 1.0147x over previous
#include <cuda_runtime.h>
#include <cstdint>

#define B_ 4
#define C_ 3
#define H_ 360
#define W_ 640
#define HP 364
#define WP 644
#define GH 52
#define GW 92
#define BP (B_*GH*GW)   /* 19136 patches */
#define FH 64           /* F_HEAD */
#define FC 32           /* F_CH  */
#define NF 64           /* N_FEATS */

// ---------------- scratch (device globals; no allocation allowed) ----------
__device__ __align__(16) float g_feat1[BP*FH*25];   // conv1 out: [p][pos25][ic64]
__device__ __align__(16) float g_feat2[BP*FH*9];    // conv2 out: [p][oc*9+pos]
__device__ __align__(16) float g_kern [BP*FC*27];   // per-patch kernels [p][864]
__device__ __align__(16) float g_bias [BP*FC];      // per-patch bias [p][32]
__device__ __align__(16) float g_ymid [B_*FC*HP*WP];     // adaptive conv out
__device__ __align__(16) float g_y3  [(size_t)B_*NF*HP*WP]; // conv3 out
__device__ __align__(16) uint32_t g_wt [25*FC*NF];  // conv3 w tf32 [tap][ic][oc]
__device__ __align__(16) uint32_t g_wt2[9*FH*FH];   // conv2 w tf32 [tap][ic][oc]
__device__ __align__(16) uint32_t g_wt4[9*NF*16];   // conv4 w tf32 [tap][ic][oc16]

__device__ __forceinline__ float rgb_mean(int c) {
    return (c == 0) ? 0.4488f*255.0f : (c == 1) ? 0.4371f*255.0f : 0.404f*255.0f;
}

__device__ __forceinline__ uint32_t tf32_bits(float f) {
    uint32_t u;
    asm("cvt.rna.tf32.f32 %0, %1;" : "=r"(u) : "f"(f));
    return u;
}

#define MMA_TF32(ACC, A0,A1,A2,A3, B0,B1) \
    asm volatile("mma.sync.aligned.m16n8k8.row.col.f32.tf32.tf32.f32 " \
        "{%0,%1,%2,%3}, {%4,%5,%6,%7}, {%8,%9}, {%0,%1,%2,%3};\n" \
        : "+f"((ACC)[0]), "+f"((ACC)[1]), "+f"((ACC)[2]), "+f"((ACC)[3]) \
        : "r"(A0), "r"(A1), "r"(A2), "r"(A3), "r"(B0), "r"(B1))

// ---------------- weight transposes (tf32 pre-conversion) ----------------
__global__ void k5w_transpose(const float* __restrict__ w3) {
    int i = blockIdx.x*256 + threadIdx.x;
    if (i >= 25*FC*NF) return;
    int tap = i / (FC*NF);
    int rem = i - tap*(FC*NF);
    int ic = rem >> 6, oc = rem & 63;
    g_wt[i] = tf32_bits(w3[(oc*FC + ic)*25 + tap]);
}
__global__ void k2w_transpose(const float* __restrict__ w2) {
    int i = blockIdx.x*256 + threadIdx.x;
    if (i >= 9*FH*FH) return;
    int tap = i / (FH*FH);
    int rem = i - tap*(FH*FH);
    int ic = rem >> 6, oc = rem & 63;
    g_wt2[i] = tf32_bits(w2[(oc*FH + ic)*9 + tap]);
}
__global__ void k6w_transpose(const float* __restrict__ w4) {
    int i = blockIdx.x*256 + threadIdx.x;
    if (i >= 9*NF*16) return;
    int tap = i / (NF*16);
    int rem = i - tap*(NF*16);
    int ic = rem >> 4, oc = rem & 15;
    float v = (oc < 12) ? w4[(oc*NF + ic)*9 + tap] : 0.f;
    g_wt4[i] = tf32_bits(v);
}

// ---------------- K1: patch extract + conv1 3x3 VALID + relu (fp32).
// [R8 verified: -130us] 4 patches x 1 warp, 2 oc/thread, weights in regs.
__global__ void __launch_bounds__(128) k1_conv1(const float* __restrict__ x,
                                                const float* __restrict__ w1,
                                                const float* __restrict__ b1) {
    __shared__ float sp[4][148];
    __shared__ float ws[FH*27];
    __shared__ float bs[FH];
    int p0 = blockIdx.x*4;
    int tid = threadIdx.x;
    int pl = tid >> 5, lane = tid & 31;
    for (int i = tid; i < FH*27; i += 128) ws[i] = w1[i];
    if (tid < FH) bs[tid] = b1[tid];
    for (int i = tid; i < 4*147; i += 128) {
        int pp = i / 147, q = i - pp*147;
        int c = q/49, rr = q%49, ii = rr/7, jj = rr%7;
        int p = p0 + pp;
        int b = p/(GH*GW); int r = p%(GH*GW); int gi = r/GW, gj = r%GW;
        int h = gi*7 + ii, w = gj*7 + jj;
        float v = 0.f;
        if (h < H_ && w < W_) v = x[((b*C_+c)*H_ + h)*W_ + w] - rgb_mean(c);
        sp[pp][q] = v;
    }
    __syncthreads();
    float wr0[27], wr1[27];
    #pragma unroll
    for (int k = 0; k < 27; k++) { wr0[k] = ws[lane*27+k]; wr1[k] = ws[(lane+32)*27+k]; }
    float bv0 = bs[lane], bv1 = bs[lane+32];
    float* dst = &g_feat1[(size_t)(p0+pl)*1600];
    #pragma unroll
    for (int q = 0; q < 25; q++) {
        int oy = q/5, ox = q%5;
        float a0 = bv0, a1 = bv1;
        #pragma unroll
        for (int c = 0; c < 3; c++)
            #pragma unroll
            for (int ky = 0; ky < 3; ky++)
                #pragma unroll
                for (int kx = 0; kx < 3; kx++) {
                    float tap = sp[pl][c*49 + (oy+ky)*7 + (ox+kx)];
                    int k = c*9 + ky*3 + kx;
                    a0 += tap*wr0[k];
                    a1 += tap*wr1[k];
                }
        dst[q*64 + lane]      = fmaxf(a0, 0.f);
        dst[q*64 + lane + 32] = fmaxf(a1, 0.f);
    }
}

// ---------------- K2: conv2 3x3 VALID (64->64) + relu — tf32 mma.
// R9 base + register prefetch of tap+1 weight slab (LDG hidden under mma).
__global__ void __launch_bounds__(128) k2_conv2(const float* __restrict__ b2) {
    __shared__ __align__(16) uint32_t sf[4*25*68];    // [pl*25+pos][ic pad 68]
    __shared__ __align__(16) uint32_t wslab[64*72];   // [ic][oc pad 72]
    int tid = threadIdx.x;
    int p0 = blockIdx.x*4;
    int warp = tid >> 5, lane = tid & 31;
    int g = lane >> 2, t = lane & 3;

    for (int i = tid; i < 4*400; i += 128) {
        int pl = i / 400, rem = i - pl*400;
        int pos = rem >> 4, c = rem & 15;
        float4 v = *(const float4*)&g_feat1[(size_t)(p0+pl)*1600 + pos*64 + 4*c];
        uint32_t* dst = &sf[(pl*25+pos)*68 + 4*c];
        dst[0]=tf32_bits(v.x); dst[1]=tf32_bits(v.y);
        dst[2]=tf32_bits(v.z); dst[3]=tf32_bits(v.w);
    }

    int rB[5];
    #pragma unroll
    for (int j = 0; j < 5; j++) {
        int col = 8*j + g;
        int cc = (col < 36) ? col : 35;
        int pl = cc/9, pos = cc - pl*9;
        int oy = pos/3, ox = pos - oy*3;
        rB[j] = pl*25 + oy*5 + ox;
    }
    float acc[5][4];
    #pragma unroll
    for (int j = 0; j < 5; j++)
        #pragma unroll
        for (int q = 0; q < 4; q++) acc[j][q] = 0.f;

    // prefetch tap 0 weights into regs (8 uint4/thread)
    uint4 wreg[8];
    #pragma unroll
    for (int u = 0; u < 8; u++) {
        int i = tid + u*128;
        wreg[u] = *(const uint4*)&g_wt2[((i>>4)<<6) + 4*(i&15)];
    }

    for (int tap = 0; tap < 9; tap++) {
        __syncthreads();   // WAR on wslab (first iter also covers sf)
        #pragma unroll
        for (int u = 0; u < 8; u++) {
            int i = tid + u*128;
            *(uint4*)&wslab[(i>>4)*72 + 4*(i&15)] = wreg[u];
        }
        if (tap < 8) {
            #pragma unroll
            for (int u = 0; u < 8; u++) {
                int i = tid + u*128;
                wreg[u] = *(const uint4*)&g_wt2[(tap+1)*4096 + ((i>>4)<<6) + 4*(i&15)];
            }
        }
        __syncthreads();
        int dtr = tap/3, dtc = tap - dtr*3;
        int roff = (dtr*5 + dtc)*68;
        #pragma unroll
        for (int ks = 0; ks < 8; ks++) {
            int kl = ks*8;
            uint32_t a0 = wslab[(kl+t)*72   + 16*warp + g];
            uint32_t a1 = wslab[(kl+t)*72   + 16*warp + g + 8];
            uint32_t a2 = wslab[(kl+t+4)*72 + 16*warp + g];
            uint32_t a3 = wslab[(kl+t+4)*72 + 16*warp + g + 8];
            #pragma unroll
            for (int j = 0; j < 5; j++) {
                const uint32_t* bp = &sf[rB[j]*68 + roff + kl + t];
                uint32_t b0 = bp[0], b1 = bp[4];
                MMA_TF32(acc[j], a0,a1,a2,a3, b0,b1);
            }
        }
    }

    int oc0 = 16*warp + g;
    float bv0 = b2[oc0], bv1 = b2[oc0+8];
    #pragma unroll
    for (int j = 0; j < 5; j++) {
        #pragma unroll
        for (int h2 = 0; h2 < 2; h2++) {
            int col = 8*j + 2*t + h2;
            if (col >= 36) continue;
            int pl = col/9, pos = col - pl*9;
            float* d = g_feat2 + (size_t)(p0+pl)*576;
            d[oc0*9 + pos]     = fmaxf(acc[j][h2]   + bv0, 0.f);
            d[(oc0+8)*9 + pos] = fmaxf(acc[j][2+h2] + bv1, 0.f);
        }
    }
}

// ---------------- K3: fused GEMM C[BP][896] = feat2[BP][576] x [wk;wb]^T + [bk;bb]
// (R7/R9 version unchanged.)
__global__ void __launch_bounds__(128) k3_gemm(const float* __restrict__ wk,
                                               const float* __restrict__ bk,
                                               const float* __restrict__ wb,
                                               const float* __restrict__ bb) {
    __shared__ uint32_t As[128*36];
    __shared__ uint32_t Bs[64*36];
    int tid = threadIdx.x;
    int warp = tid >> 5, lane = tid & 31;
    int g = lane >> 2, t = lane & 3;
    int m0 = blockIdx.y*128, n0 = blockIdx.x*64;
    int c = tid & 7, r0 = tid >> 3;

    float acc[2][8][4];
    #pragma unroll
    for (int mt = 0; mt < 2; mt++)
        #pragma unroll
        for (int j = 0; j < 8; j++)
            #pragma unroll
            for (int q = 0; q < 4; q++) acc[mt][j][q] = 0.f;

    for (int k0 = 0; k0 < 576; k0 += 32) {
        __syncthreads();
        #pragma unroll
        for (int rr = r0; rr < 128; rr += 16) {
            int m = m0 + rr;
            float4 v = make_float4(0.f,0.f,0.f,0.f);
            if (m < BP) v = *(const float4*)&g_feat2[(size_t)m*576 + k0 + 4*c];
            uint32_t* dst = &As[rr*36 + 4*c];
            dst[0]=tf32_bits(v.x); dst[1]=tf32_bits(v.y);
            dst[2]=tf32_bits(v.z); dst[3]=tf32_bits(v.w);
        }
        #pragma unroll
        for (int rr = r0; rr < 64; rr += 16) {
            int n = n0 + rr;
            const float* src = (n < 864) ? &wk[(size_t)n*576] : &wb[(size_t)(n-864)*576];
            float4 v = *(const float4*)&src[k0 + 4*c];
            uint32_t* dst = &Bs[rr*36 + 4*c];
            dst[0]=tf32_bits(v.x); dst[1]=tf32_bits(v.y);
            dst[2]=tf32_bits(v.z); dst[3]=tf32_bits(v.w);
        }
        __syncthreads();
        #pragma unroll
        for (int ks = 0; ks < 4; ks++) {
            int kl = ks*8;
            uint32_t bf[8][2];
            #pragma unroll
            for (int j = 0; j < 8; j++) {
                bf[j][0] = Bs[(8*j+g)*36 + kl + t];
                bf[j][1] = Bs[(8*j+g)*36 + kl + t + 4];
            }
            #pragma unroll
            for (int mt = 0; mt < 2; mt++) {
                int mb = 32*warp + 16*mt;
                uint32_t a0 = As[(mb+g)*36   + kl + t];
                uint32_t a1 = As[(mb+g+8)*36 + kl + t];
                uint32_t a2 = As[(mb+g)*36   + kl + t + 4];
                uint32_t a3 = As[(mb+g+8)*36 + kl + t + 4];
                #pragma unroll
                for (int j = 0; j < 8; j++)
                    MMA_TF32(acc[mt][j], a0,a1,a2,a3, bf[j][0], bf[j][1]);
            }
        }
    }

    #pragma unroll
    for (int mt = 0; mt < 2; mt++) {
        int m = m0 + 32*warp + 16*mt + g;
        #pragma unroll
        for (int j = 0; j < 8; j++) {
            #pragma unroll
            for (int h2 = 0; h2 < 2; h2++) {
                int n = n0 + 8*j + 2*t + h2;
                float v0 = acc[mt][j][h2], v1 = acc[mt][j][2+h2];
                if (n < 864) {
                    float bv = bk[n];
                    if (m < BP)     g_kern[(size_t)m*864 + n]     = v0 + bv;
                    if (m+8 < BP)   g_kern[(size_t)(m+8)*864 + n] = v1 + bv;
                } else {
                    float bv = bb[n-864];
                    if (m < BP)     g_bias[(size_t)m*32 + (n-864)]     = v0 + bv;
                    if (m+8 < BP)   g_bias[(size_t)(m+8)*32 + (n-864)] = v1 + bv;
                }
            }
        }
    }
}

// ---------------- K4: adaptive per-patch 3x3 conv — 2 patches/block (R8).
__global__ void __launch_bounds__(128) k4_adapt(const float* __restrict__ x) {
    __shared__ float ks[2][FC*27];
    __shared__ float bsm[2][FC];
    __shared__ float xs[2][C_*81];
    int p0 = blockIdx.x*2;
    int tid = threadIdx.x;
    for (int i = tid; i < 2*FC*27; i += 128) {
        int pp = i / (FC*27), k = i % (FC*27);
        ks[pp][k] = g_kern[(size_t)(p0+pp)*(FC*27) + k];
    }
    if (tid < 2*FC) bsm[tid>>5][tid&31] = g_bias[(size_t)(p0+(tid>>5))*FC + (tid&31)];
    for (int i = tid; i < 2*C_*81; i += 128) xs[i/243][i%243] = 0.f;
    __syncthreads();
    for (int i = tid; i < 2*C_*49; i += 128) {
        int pp = i/147, q = i%147;
        int c = q/49, rr = q%49, ii = rr/7, jj = rr%7;
        int p = p0 + pp;
        int b = p/(GH*GW); int r = p%(GH*GW); int gi = r/GW, gj = r%GW;
        int h = gi*7+ii, w = gj*7+jj;
        float v = 0.f;
        if (h < H_ && w < W_) v = x[((b*C_+c)*H_+h)*W_+w] - rgb_mean(c);
        xs[pp][c*81 + (ii+1)*9 + (jj+1)] = v;
    }
    __syncthreads();
    if (tid < 98) {
        int pl = tid/49, q = tid - pl*49;
        int i = q/7, j = q%7;
        float v[27];
        #pragma unroll
        for (int c = 0; c < 3; c++)
            #pragma unroll
            for (int di = 0; di < 3; di++)
                #pragma unroll
                for (int dj = 0; dj < 3; dj++)
                    v[c*9+di*3+dj] = xs[pl][c*81 + (i+di)*9 + (j+dj)];
        int p = p0 + pl;
        int b = p/(GH*GW); int r = p%(GH*GW); int gi = r/GW, gj = r%GW;
        int h = gi*7+i, w = gj*7+j;
        for (int f = 0; f < FC; f++) {
            float acc = bsm[pl][f];
            #pragma unroll
            for (int k = 0; k < 27; k++) acc += ks[pl][f*27+k]*v[k];
            g_ymid[((b*FC+f)*HP + h)*WP + w] = acc;
        }
    }
}

// ---------------- K5: conv3 5x5 pad2, 32->64, relu — tf32 mma.
// R9 base + register prefetch of tap+1 weight slab (4 uint4/thread).
__global__ void __launch_bounds__(128) k5_conv3(const float* __restrict__ b3) {
    __shared__ __align__(16) uint32_t tileS[12*20*36];
    __shared__ __align__(16) uint32_t wslab[32*72];
    __shared__ float sbias[NF];
    int b  = blockIdx.z;
    int by = blockIdx.y, bx = blockIdx.x;
    int tid = threadIdx.x;
    int warp = tid >> 5, lane = tid & 31;
    int g = lane >> 2, t = lane & 3;
    int gh0 = by*8 - 2, gw0 = bx*16 - 2;

    for (int i = tid; i < FC*240; i += 128) {
        int ic = i / 240, pos = i - ic*240;
        int r = pos / 20, c = pos - r*20;
        int hh = gh0 + r, ww = gw0 + c;
        float v = 0.f;
        if (hh >= 0 && hh < HP && ww >= 0 && ww < WP)
            v = g_ymid[((b*FC + ic)*HP + hh)*WP + ww];
        tileS[(r*20 + c)*36 + ic] = tf32_bits(v);
    }
    if (tid < NF) sbias[tid] = b3[tid];

    float acc[16][4];
    #pragma unroll
    for (int j = 0; j < 16; j++)
        #pragma unroll
        for (int q = 0; q < 4; q++) acc[j][q] = 0.f;

    // prefetch tap 0 weights (4 uint4/thread)
    uint4 wreg[4];
    #pragma unroll
    for (int u = 0; u < 4; u++) {
        int i = tid + u*128;
        wreg[u] = *(const uint4*)&g_wt[((i>>4)<<6) + 4*(i&15)];
    }

    for (int tap = 0; tap < 25; tap++) {
        __syncthreads();   // WAR on wslab (first iter also covers tileS/sbias)
        #pragma unroll
        for (int u = 0; u < 4; u++) {
            int i = tid + u*128;
            *(uint4*)&wslab[(i>>4)*72 + 4*(i&15)] = wreg[u];
        }
        if (tap < 24) {
            #pragma unroll
            for (int u = 0; u < 4; u++) {
                int i = tid + u*128;
                wreg[u] = *(const uint4*)&g_wt[(tap+1)*2048 + ((i>>4)<<6) + 4*(i&15)];
            }
        }
        __syncthreads();
        int dtr = tap / 5, dtc = tap - dtr*5;
        #pragma unroll
        for (int ks = 0; ks < 4; ks++) {
            int ic0 = ks*8;
            uint32_t a0 = wslab[(ic0+t)*72   + 16*warp + g];
            uint32_t a1 = wslab[(ic0+t)*72   + 16*warp + g + 8];
            uint32_t a2 = wslab[(ic0+t+4)*72 + 16*warp + g];
            uint32_t a3 = wslab[(ic0+t+4)*72 + 16*warp + g + 8];
            #pragma unroll
            for (int j = 0; j < 16; j++) {
                int jr = j >> 1, jc = (j & 1)*8;
                const uint32_t* bp = &tileS[((jr+dtr)*20 + jc + g + dtc)*36 + ic0 + t];
                uint32_t b0 = bp[0], b1 = bp[4];
                MMA_TF32(acc[j], a0,a1,a2,a3, b0,b1);
            }
        }
    }

    int oc0 = 16*warp + g;
    float bv0 = sbias[oc0], bv1 = sbias[oc0 + 8];
    #pragma unroll
    for (int j = 0; j < 16; j++) {
        int jr = j >> 1, jc = (j & 1)*8;
        int py = by*8 + jr;
        if (py >= HP) continue;
        int px = bx*16 + jc + 2*t;
        float* base0 = g_y3 + (((size_t)b*NF + oc0)*HP + py)*WP;
        float* base1 = g_y3 + (((size_t)b*NF + oc0 + 8)*HP + py)*WP;
        if (px < WP) {
            base0[px] = fmaxf(acc[j][0] + bv0, 0.f);
            base1[px] = fmaxf(acc[j][2] + bv1, 0.f);
        }
        if (px + 1 < WP) {
            base0[px+1] = fmaxf(acc[j][1] + bv0, 0.f);
            base1[px+1] = fmaxf(acc[j][3] + bv1, 0.f);
        }
    }
}

// ---------------- K6: conv4 3x3 pad1 (64->12) + pixel-shuffle — tf32 mma.
// R9 base + register prefetch of the next weight slab (crosses half boundary).
__global__ void __launch_bounds__(128) k6_conv4(const float* __restrict__ b4,
                                                float* __restrict__ out) {
    __shared__ __align__(16) uint32_t tileS[180*36];   // 25.9 KB
    __shared__ __align__(16) uint32_t wslab[32*24];    //  3 KB
    __shared__ float sbias[16];
    int b  = blockIdx.z;
    int by = blockIdx.y, bx = blockIdx.x;
    int tid = threadIdx.x;
    int warp = tid >> 5, lane = tid & 31;
    int g = lane >> 2, t = lane & 3;
    int gh0 = by*8 - 1, gw0 = bx*16 - 1;
    if (tid < 16) sbias[tid] = (tid < 12) ? b4[tid] : 0.f;

    float acc[4][4];
    #pragma unroll
    for (int j = 0; j < 4; j++)
        #pragma unroll
        for (int q = 0; q < 4; q++) acc[j][q] = 0.f;

    // weight prefetch: linear tap-queue index tq = half*9 + tap (0..17)
    int wi_icl = tid >> 2, wi_c = tid & 3;
    uint4 wreg = *(const uint4*)&g_wt4[wi_icl*16 + 4*wi_c];   // tq = 0

    for (int half = 0; half < 2; half++) {
        int icg = half*32;
        __syncthreads();   // WAR on tileS
        for (int i = tid; i < 32*180; i += 128) {
            int icl = i / 180, pos = i - icl*180;
            int r = pos / 18, c = pos - r*18;
            int hh = gh0 + r, ww = gw0 + c;
            float v = 0.f;
            if (hh >= 0 && ww >= 0)
                v = g_y3[(((size_t)b*NF + icg + icl)*HP + hh)*WP + ww];
            tileS[pos*36 + icl] = tf32_bits(v);
        }
        for (int tap = 0; tap < 9; tap++) {
            __syncthreads();   // WAR on wslab (first iter also covers tileS)
            *(uint4*)&wslab[wi_icl*24 + 4*wi_c] = wreg;
            int tq = half*9 + tap;
            if (tq < 17) {
                int tqn = tq + 1;
                int tpn = tqn % 9, icgn = (tqn / 9)*32;
                wreg = *(const uint4*)&g_wt4[tpn*(NF*16) + (icgn + wi_icl)*16 + 4*wi_c];
            }
            __syncthreads();
            int dtr = tap/3, dtc = tap - dtr*3;
            #pragma unroll
            for (int ks = 0; ks < 4; ks++) {
                int kl = ks*8;
                uint32_t a0 = wslab[(kl+t)*24   + g];
                uint32_t a1 = wslab[(kl+t)*24   + g + 8];
                uint32_t a2 = wslab[(kl+t+4)*24 + g];
                uint32_t a3 = wslab[(kl+t+4)*24 + g + 8];
                #pragma unroll
                for (int jj = 0; jj < 4; jj++) {
                    int jn = warp*4 + jj;
                    int jr = jn >> 1, jc = (jn & 1)*8;
                    const uint32_t* bp = &tileS[((jr+dtr)*18 + jc + g + dtc)*36 + kl + t];
                    uint32_t b0 = bp[0], b1 = bp[4];
                    MMA_TF32(acc[jj], a0,a1,a2,a3, b0,b1);
                }
            }
        }
    }

    #pragma unroll
    for (int jj = 0; jj < 4; jj++) {
        int jn = warp*4 + jj;
        int jr = jn >> 1, jc = (jn & 1)*8;
        int h = by*8 + jr;            // < 360
        int px = bx*16 + jc + 2*t;    // < 640
        #pragma unroll
        for (int mrow = 0; mrow < 2; mrow++) {
            int o = g + 8*mrow;
            if (o >= 12) continue;
            int co = o >> 2, s1 = (o >> 1) & 1, s2 = o & 1;
            float bv = sbias[o] + rgb_mean(co);
            float* dst = out + ((b*3+co)*720 + 2*h + s1)*1280;
            dst[2*px + s2]     = acc[jj][2*mrow]   + bv;
            dst[2*(px+1) + s2] = acc[jj][2*mrow+1] + bv;
        }
    }
}

// ---------------- launch ----------------
extern "C" void kernel_launch(void* const* d_in, const int* in_sizes, int n_in,
                              void* d_out, int out_size) {
    const float* x  = (const float*)d_in[0];
    const float* w1 = (const float*)d_in[1];
    const float* b1 = (const float*)d_in[2];
    const float* w2 = (const float*)d_in[3];
    const float* b2 = (const float*)d_in[4];
    const float* wk = (const float*)d_in[5];
    const float* bk = (const float*)d_in[6];
    const float* wb = (const float*)d_in[7];
    const float* bb = (const float*)d_in[8];
    const float* w3 = (const float*)d_in[9];
    const float* b3 = (const float*)d_in[10];
    const float* w4 = (const float*)d_in[11];
    const float* b4 = (const float*)d_in[12];
    float* out = (float*)d_out;

    k5w_transpose<<<(25*FC*NF + 255)/256, 256>>>(w3);
    k2w_transpose<<<(9*FH*FH + 255)/256, 256>>>(w2);
    k6w_transpose<<<(9*NF*16 + 255)/256, 256>>>(w4);
    k1_conv1<<<BP/4, 128>>>(x, w1, b1);
    k2_conv2<<<BP/4, 128>>>(b2);
    k3_gemm<<<dim3(14, (BP+127)/128), 128>>>(wk, bk, wb, bb);
    k4_adapt<<<BP/2, 128>>>(x);
    k5_conv3<<<dim3((WP+15)/16, (HP+7)/8, B_), 128>>>(b3);
    k6_conv4<<<dim3(W_/16, H_/8, B_), 128>>>(b4, out);
}

// round 11
// speedup vs baseline: 1.1415x; 1.0350x over previous
#include <cuda_runtime.h>
#include <cstdint>

#define B_ 4
#define C_ 3
#define H_ 360
#define W_ 640
#define HP 364
#define WP 644
#define GH 52
#define GW 92
#define BP (B_*GH*GW)   /* 19136 patches */
#define FH 64           /* F_HEAD */
#define FC 32           /* F_CH  */
#define NF 64           /* N_FEATS */

// ---------------- scratch (device globals; no allocation allowed) ----------
__device__ __align__(16) float g_feat2[BP*FH*9];    // conv2 out: [p][oc*9+pos]
__device__ __align__(16) float g_kern [BP*FC*27];   // per-patch kernels [p][864]
__device__ __align__(16) float g_bias [BP*FC];      // per-patch bias [p][32]
__device__ __align__(16) float g_ymid [B_*FC*HP*WP];     // adaptive conv out
__device__ __align__(16) float g_y3  [(size_t)B_*NF*HP*WP]; // conv3 out
__device__ __align__(16) uint32_t g_wt [25*FC*NF];  // conv3 w tf32 [tap][ic][oc]
__device__ __align__(16) uint32_t g_wt2[9*FH*FH];   // conv2 w tf32 [tap][ic][oc]
__device__ __align__(16) uint32_t g_wt4[9*NF*16];   // conv4 w tf32 [tap][ic][oc16]

__device__ __forceinline__ float rgb_mean(int c) {
    return (c == 0) ? 0.4488f*255.0f : (c == 1) ? 0.4371f*255.0f : 0.404f*255.0f;
}

__device__ __forceinline__ uint32_t tf32_bits(float f) {
    uint32_t u;
    asm("cvt.rna.tf32.f32 %0, %1;" : "=r"(u) : "f"(f));
    return u;
}

#define MMA_TF32(ACC, A0,A1,A2,A3, B0,B1) \
    asm volatile("mma.sync.aligned.m16n8k8.row.col.f32.tf32.tf32.f32 " \
        "{%0,%1,%2,%3}, {%4,%5,%6,%7}, {%8,%9}, {%0,%1,%2,%3};\n" \
        : "+f"((ACC)[0]), "+f"((ACC)[1]), "+f"((ACC)[2]), "+f"((ACC)[3]) \
        : "r"(A0), "r"(A1), "r"(A2), "r"(A3), "r"(B0), "r"(B1))

// ---------------- merged weight transpose (tf32 pre-conversion, 1 launch) ----
__global__ void kw_transpose(const float* __restrict__ w3,
                             const float* __restrict__ w2,
                             const float* __restrict__ w4) {
    int i = blockIdx.x*256 + threadIdx.x;
    if (i < 25*FC*NF) {                       // conv3: [tap][ic][oc64]
        int tap = i / (FC*NF);
        int rem = i - tap*(FC*NF);
        int ic = rem >> 6, oc = rem & 63;
        g_wt[i] = tf32_bits(w3[(oc*FC + ic)*25 + tap]);
    }
    if (i < 9*FH*FH) {                        // conv2: [tap][ic][oc64]
        int tap = i / (FH*FH);
        int rem = i - tap*(FH*FH);
        int ic = rem >> 6, oc = rem & 63;
        g_wt2[i] = tf32_bits(w2[(oc*FH + ic)*9 + tap]);
    }
    if (i < 9*NF*16) {                        // conv4: [tap][ic][oc16 padded]
        int tap = i / (NF*16);
        int rem = i - tap*(NF*16);
        int ic = rem >> 4, oc = rem & 15;
        float v = (oc < 12) ? w4[(oc*NF + ic)*9 + tap] : 0.f;
        g_wt4[i] = tf32_bits(v);
    }
}

// ---------------- K12: FUSED conv1 (fp32, reg weights) + conv2 (tf32 mma).
// 128 thr = 4 patches. Phase 1: warp pl computes conv1 for patch pl (2 oc per
// thread, weights in 54 regs), writes relu'd tf32 straight into sf (no
// g_feat1 round-trip: saves ~244 MB DRAM). Phase 2: R10 k2 mma body.
__global__ void __launch_bounds__(128) k12_conv12(const float* __restrict__ x,
                                                  const float* __restrict__ w1,
                                                  const float* __restrict__ b1,
                                                  const float* __restrict__ b2) {
    __shared__ float sp[4][148];
    __shared__ float ws[FH*27];
    __shared__ float bs[FH];
    __shared__ __align__(16) uint32_t sf[4*25*68];    // [pl*25+pos][ic pad 68]
    __shared__ __align__(16) uint32_t wslab[64*72];   // [ic][oc pad 72]
    int tid = threadIdx.x;
    int p0 = blockIdx.x*4;
    int warp = tid >> 5, lane = tid & 31;
    int g = lane >> 2, t = lane & 3;
    int pl = warp;

    // ---- phase 1: stage patch + conv1 weights
    for (int i = tid; i < FH*27; i += 128) ws[i] = w1[i];
    if (tid < FH) bs[tid] = b1[tid];
    for (int i = tid; i < 4*147; i += 128) {
        int pp = i / 147, q = i - pp*147;
        int c = q/49, rr = q%49, ii = rr/7, jj = rr%7;
        int p = p0 + pp;
        int b = p/(GH*GW); int r = p%(GH*GW); int gi = r/GW, gj = r%GW;
        int h = gi*7 + ii, w = gj*7 + jj;
        float v = 0.f;
        if (h < H_ && w < W_) v = x[((b*C_+c)*H_ + h)*W_ + w] - rgb_mean(c);
        sp[pp][q] = v;
    }
    __syncthreads();
    {
        float wr0[27], wr1[27];
        #pragma unroll
        for (int k = 0; k < 27; k++) { wr0[k] = ws[lane*27+k]; wr1[k] = ws[(lane+32)*27+k]; }
        float bv0 = bs[lane], bv1 = bs[lane+32];
        #pragma unroll
        for (int q = 0; q < 25; q++) {
            int oy = q/5, ox = q%5;
            float a0 = bv0, a1 = bv1;
            #pragma unroll
            for (int c = 0; c < 3; c++)
                #pragma unroll
                for (int ky = 0; ky < 3; ky++)
                    #pragma unroll
                    for (int kx = 0; kx < 3; kx++) {
                        float tap = sp[pl][c*49 + (oy+ky)*7 + (ox+kx)];
                        int k = c*9 + ky*3 + kx;
                        a0 += tap*wr0[k];
                        a1 += tap*wr1[k];
                    }
            sf[(pl*25+q)*68 + lane]      = tf32_bits(fmaxf(a0, 0.f));
            sf[(pl*25+q)*68 + lane + 32] = tf32_bits(fmaxf(a1, 0.f));
        }
    }

    // prefetch tap 0 conv2 weights into regs (8 uint4/thread) while others finish
    uint4 wreg[8];
    #pragma unroll
    for (int u = 0; u < 8; u++) {
        int i = tid + u*128;
        wreg[u] = *(const uint4*)&g_wt2[((i>>4)<<6) + 4*(i&15)];
    }
    __syncthreads();   // sf fully written

    // ---- phase 2: conv2 tf32 mma (R10 body)
    int rB[5];
    #pragma unroll
    for (int j = 0; j < 5; j++) {
        int col = 8*j + g;
        int cc = (col < 36) ? col : 35;
        int plc = cc/9, pos = cc - plc*9;
        int oy = pos/3, ox = pos - oy*3;
        rB[j] = plc*25 + oy*5 + ox;
    }
    float acc[5][4];
    #pragma unroll
    for (int j = 0; j < 5; j++)
        #pragma unroll
        for (int q = 0; q < 4; q++) acc[j][q] = 0.f;

    for (int tap = 0; tap < 9; tap++) {
        if (tap) __syncthreads();   // WAR on wslab
        #pragma unroll
        for (int u = 0; u < 8; u++) {
            int i = tid + u*128;
            *(uint4*)&wslab[(i>>4)*72 + 4*(i&15)] = wreg[u];
        }
        if (tap < 8) {
            #pragma unroll
            for (int u = 0; u < 8; u++) {
                int i = tid + u*128;
                wreg[u] = *(const uint4*)&g_wt2[(tap+1)*4096 + ((i>>4)<<6) + 4*(i&15)];
            }
        }
        __syncthreads();
        int dtr = tap/3, dtc = tap - dtr*3;
        int roff = (dtr*5 + dtc)*68;
        #pragma unroll
        for (int ks = 0; ks < 8; ks++) {
            int kl = ks*8;
            uint32_t a0 = wslab[(kl+t)*72   + 16*warp + g];
            uint32_t a1 = wslab[(kl+t)*72   + 16*warp + g + 8];
            uint32_t a2 = wslab[(kl+t+4)*72 + 16*warp + g];
            uint32_t a3 = wslab[(kl+t+4)*72 + 16*warp + g + 8];
            #pragma unroll
            for (int j = 0; j < 5; j++) {
                const uint32_t* bp = &sf[rB[j]*68 + roff + kl + t];
                uint32_t b0 = bp[0], b1 = bp[4];
                MMA_TF32(acc[j], a0,a1,a2,a3, b0,b1);
            }
        }
    }

    int oc0 = 16*warp + g;
    float bv0 = b2[oc0], bv1 = b2[oc0+8];
    #pragma unroll
    for (int j = 0; j < 5; j++) {
        #pragma unroll
        for (int h2 = 0; h2 < 2; h2++) {
            int col = 8*j + 2*t + h2;
            if (col >= 36) continue;
            int plc = col/9, pos = col - plc*9;
            float* d = g_feat2 + (size_t)(p0+plc)*576;
            d[oc0*9 + pos]     = fmaxf(acc[j][h2]   + bv0, 0.f);
            d[(oc0+8)*9 + pos] = fmaxf(acc[j][2+h2] + bv1, 0.f);
        }
    }
}

// ---------------- K3: fused GEMM C[BP][896] = feat2[BP][576] x [wk;wb]^T + [bk;bb]
__global__ void __launch_bounds__(128) k3_gemm(const float* __restrict__ wk,
                                               const float* __restrict__ bk,
                                               const float* __restrict__ wb,
                                               const float* __restrict__ bb) {
    __shared__ uint32_t As[128*36];
    __shared__ uint32_t Bs[64*36];
    int tid = threadIdx.x;
    int warp = tid >> 5, lane = tid & 31;
    int g = lane >> 2, t = lane & 3;
    int m0 = blockIdx.y*128, n0 = blockIdx.x*64;
    int c = tid & 7, r0 = tid >> 3;

    float acc[2][8][4];
    #pragma unroll
    for (int mt = 0; mt < 2; mt++)
        #pragma unroll
        for (int j = 0; j < 8; j++)
            #pragma unroll
            for (int q = 0; q < 4; q++) acc[mt][j][q] = 0.f;

    for (int k0 = 0; k0 < 576; k0 += 32) {
        __syncthreads();
        #pragma unroll
        for (int rr = r0; rr < 128; rr += 16) {
            int m = m0 + rr;
            float4 v = make_float4(0.f,0.f,0.f,0.f);
            if (m < BP) v = *(const float4*)&g_feat2[(size_t)m*576 + k0 + 4*c];
            uint32_t* dst = &As[rr*36 + 4*c];
            dst[0]=tf32_bits(v.x); dst[1]=tf32_bits(v.y);
            dst[2]=tf32_bits(v.z); dst[3]=tf32_bits(v.w);
        }
        #pragma unroll
        for (int rr = r0; rr < 64; rr += 16) {
            int n = n0 + rr;
            const float* src = (n < 864) ? &wk[(size_t)n*576] : &wb[(size_t)(n-864)*576];
            float4 v = *(const float4*)&src[k0 + 4*c];
            uint32_t* dst = &Bs[rr*36 + 4*c];
            dst[0]=tf32_bits(v.x); dst[1]=tf32_bits(v.y);
            dst[2]=tf32_bits(v.z); dst[3]=tf32_bits(v.w);
        }
        __syncthreads();
        #pragma unroll
        for (int ks = 0; ks < 4; ks++) {
            int kl = ks*8;
            uint32_t bf[8][2];
            #pragma unroll
            for (int j = 0; j < 8; j++) {
                bf[j][0] = Bs[(8*j+g)*36 + kl + t];
                bf[j][1] = Bs[(8*j+g)*36 + kl + t + 4];
            }
            #pragma unroll
            for (int mt = 0; mt < 2; mt++) {
                int mb = 32*warp + 16*mt;
                uint32_t a0 = As[(mb+g)*36   + kl + t];
                uint32_t a1 = As[(mb+g+8)*36 + kl + t];
                uint32_t a2 = As[(mb+g)*36   + kl + t + 4];
                uint32_t a3 = As[(mb+g+8)*36 + kl + t + 4];
                #pragma unroll
                for (int j = 0; j < 8; j++)
                    MMA_TF32(acc[mt][j], a0,a1,a2,a3, bf[j][0], bf[j][1]);
            }
        }
    }

    #pragma unroll
    for (int mt = 0; mt < 2; mt++) {
        int m = m0 + 32*warp + 16*mt + g;
        #pragma unroll
        for (int j = 0; j < 8; j++) {
            #pragma unroll
            for (int h2 = 0; h2 < 2; h2++) {
                int n = n0 + 8*j + 2*t + h2;
                float v0 = acc[mt][j][h2], v1 = acc[mt][j][2+h2];
                if (n < 864) {
                    float bv = bk[n];
                    if (m < BP)     g_kern[(size_t)m*864 + n]     = v0 + bv;
                    if (m+8 < BP)   g_kern[(size_t)(m+8)*864 + n] = v1 + bv;
                } else {
                    float bv = bb[n-864];
                    if (m < BP)     g_bias[(size_t)m*32 + (n-864)]     = v0 + bv;
                    if (m+8 < BP)   g_bias[(size_t)(m+8)*32 + (n-864)] = v1 + bv;
                }
            }
        }
    }
}

// ---------------- K4: adaptive per-patch 3x3 conv — 2 patches/block (R8).
__global__ void __launch_bounds__(128) k4_adapt(const float* __restrict__ x) {
    __shared__ float ks[2][FC*27];
    __shared__ float bsm[2][FC];
    __shared__ float xs[2][C_*81];
    int p0 = blockIdx.x*2;
    int tid = threadIdx.x;
    for (int i = tid; i < 2*FC*27; i += 128) {
        int pp = i / (FC*27), k = i % (FC*27);
        ks[pp][k] = g_kern[(size_t)(p0+pp)*(FC*27) + k];
    }
    if (tid < 2*FC) bsm[tid>>5][tid&31] = g_bias[(size_t)(p0+(tid>>5))*FC + (tid&31)];
    for (int i = tid; i < 2*C_*81; i += 128) xs[i/243][i%243] = 0.f;
    __syncthreads();
    for (int i = tid; i < 2*C_*49; i += 128) {
        int pp = i/147, q = i%147;
        int c = q/49, rr = q%49, ii = rr/7, jj = rr%7;
        int p = p0 + pp;
        int b = p/(GH*GW); int r = p%(GH*GW); int gi = r/GW, gj = r%GW;
        int h = gi*7+ii, w = gj*7+jj;
        float v = 0.f;
        if (h < H_ && w < W_) v = x[((b*C_+c)*H_+h)*W_+w] - rgb_mean(c);
        xs[pp][c*81 + (ii+1)*9 + (jj+1)] = v;
    }
    __syncthreads();
    if (tid < 98) {
        int pl = tid/49, q = tid - pl*49;
        int i = q/7, j = q%7;
        float v[27];
        #pragma unroll
        for (int c = 0; c < 3; c++)
            #pragma unroll
            for (int di = 0; di < 3; di++)
                #pragma unroll
                for (int dj = 0; dj < 3; dj++)
                    v[c*9+di*3+dj] = xs[pl][c*81 + (i+di)*9 + (j+dj)];
        int p = p0 + pl;
        int b = p/(GH*GW); int r = p%(GH*GW); int gi = r/GW, gj = r%GW;
        int h = gi*7+i, w = gj*7+j;
        for (int f = 0; f < FC; f++) {
            float acc = bsm[pl][f];
            #pragma unroll
            for (int k = 0; k < 27; k++) acc += ks[pl][f*27+k]*v[k];
            g_ymid[((b*FC+f)*HP + h)*WP + w] = acc;
        }
    }
}

// ---------------- K5: conv3 5x5 pad2, 32->64, relu — tf32 mma (R10 version).
__global__ void __launch_bounds__(128) k5_conv3(const float* __restrict__ b3) {
    __shared__ __align__(16) uint32_t tileS[12*20*36];
    __shared__ __align__(16) uint32_t wslab[32*72];
    __shared__ float sbias[NF];
    int b  = blockIdx.z;
    int by = blockIdx.y, bx = blockIdx.x;
    int tid = threadIdx.x;
    int warp = tid >> 5, lane = tid & 31;
    int g = lane >> 2, t = lane & 3;
    int gh0 = by*8 - 2, gw0 = bx*16 - 2;

    for (int i = tid; i < FC*240; i += 128) {
        int ic = i / 240, pos = i - ic*240;
        int r = pos / 20, c = pos - r*20;
        int hh = gh0 + r, ww = gw0 + c;
        float v = 0.f;
        if (hh >= 0 && hh < HP && ww >= 0 && ww < WP)
            v = g_ymid[((b*FC + ic)*HP + hh)*WP + ww];
        tileS[(r*20 + c)*36 + ic] = tf32_bits(v);
    }
    if (tid < NF) sbias[tid] = b3[tid];

    float acc[16][4];
    #pragma unroll
    for (int j = 0; j < 16; j++)
        #pragma unroll
        for (int q = 0; q < 4; q++) acc[j][q] = 0.f;

    uint4 wreg[4];
    #pragma unroll
    for (int u = 0; u < 4; u++) {
        int i = tid + u*128;
        wreg[u] = *(const uint4*)&g_wt[((i>>4)<<6) + 4*(i&15)];
    }

    for (int tap = 0; tap < 25; tap++) {
        __syncthreads();   // WAR on wslab (first iter also covers tileS/sbias)
        #pragma unroll
        for (int u = 0; u < 4; u++) {
            int i = tid + u*128;
            *(uint4*)&wslab[(i>>4)*72 + 4*(i&15)] = wreg[u];
        }
        if (tap < 24) {
            #pragma unroll
            for (int u = 0; u < 4; u++) {
                int i = tid + u*128;
                wreg[u] = *(const uint4*)&g_wt[(tap+1)*2048 + ((i>>4)<<6) + 4*(i&15)];
            }
        }
        __syncthreads();
        int dtr = tap / 5, dtc = tap - dtr*5;
        #pragma unroll
        for (int ks = 0; ks < 4; ks++) {
            int ic0 = ks*8;
            uint32_t a0 = wslab[(ic0+t)*72   + 16*warp + g];
            uint32_t a1 = wslab[(ic0+t)*72   + 16*warp + g + 8];
            uint32_t a2 = wslab[(ic0+t+4)*72 + 16*warp + g];
            uint32_t a3 = wslab[(ic0+t+4)*72 + 16*warp + g + 8];
            #pragma unroll
            for (int j = 0; j < 16; j++) {
                int jr = j >> 1, jc = (j & 1)*8;
                const uint32_t* bp = &tileS[((jr+dtr)*20 + jc + g + dtc)*36 + ic0 + t];
                uint32_t b0 = bp[0], b1 = bp[4];
                MMA_TF32(acc[j], a0,a1,a2,a3, b0,b1);
            }
        }
    }

    int oc0 = 16*warp + g;
    float bv0 = sbias[oc0], bv1 = sbias[oc0 + 8];
    #pragma unroll
    for (int j = 0; j < 16; j++) {
        int jr = j >> 1, jc = (j & 1)*8;
        int py = by*8 + jr;
        if (py >= HP) continue;
        int px = bx*16 + jc + 2*t;
        float* base0 = g_y3 + (((size_t)b*NF + oc0)*HP + py)*WP;
        float* base1 = g_y3 + (((size_t)b*NF + oc0 + 8)*HP + py)*WP;
        if (px < WP) {
            base0[px] = fmaxf(acc[j][0] + bv0, 0.f);
            base1[px] = fmaxf(acc[j][2] + bv1, 0.f);
        }
        if (px + 1 < WP) {
            base0[px+1] = fmaxf(acc[j][1] + bv0, 0.f);
            base1[px+1] = fmaxf(acc[j][3] + bv1, 0.f);
        }
    }
}

// ---------------- K6: conv4 3x3 pad1 (64->12) + pixel-shuffle — tf32 mma (R10).
__global__ void __launch_bounds__(128) k6_conv4(const float* __restrict__ b4,
                                                float* __restrict__ out) {
    __shared__ __align__(16) uint32_t tileS[180*36];   // 25.9 KB
    __shared__ __align__(16) uint32_t wslab[32*24];    //  3 KB
    __shared__ float sbias[16];
    int b  = blockIdx.z;
    int by = blockIdx.y, bx = blockIdx.x;
    int tid = threadIdx.x;
    int warp = tid >> 5, lane = tid & 31;
    int g = lane >> 2, t = lane & 3;
    int gh0 = by*8 - 1, gw0 = bx*16 - 1;
    if (tid < 16) sbias[tid] = (tid < 12) ? b4[tid] : 0.f;

    float acc[4][4];
    #pragma unroll
    for (int j = 0; j < 4; j++)
        #pragma unroll
        for (int q = 0; q < 4; q++) acc[j][q] = 0.f;

    int wi_icl = tid >> 2, wi_c = tid & 3;
    uint4 wreg = *(const uint4*)&g_wt4[wi_icl*16 + 4*wi_c];   // tq = 0

    for (int half = 0; half < 2; half++) {
        int icg = half*32;
        __syncthreads();   // WAR on tileS
        for (int i = tid; i < 32*180; i += 128) {
            int icl = i / 180, pos = i - icl*180;
            int r = pos / 18, c = pos - r*18;
            int hh = gh0 + r, ww = gw0 + c;
            float v = 0.f;
            if (hh >= 0 && ww >= 0)
                v = g_y3[(((size_t)b*NF + icg + icl)*HP + hh)*WP + ww];
            tileS[pos*36 + icl] = tf32_bits(v);
        }
        for (int tap = 0; tap < 9; tap++) {
            __syncthreads();   // WAR on wslab (first iter also covers tileS)
            *(uint4*)&wslab[wi_icl*24 + 4*wi_c] = wreg;
            int tq = half*9 + tap;
            if (tq < 17) {
                int tqn = tq + 1;
                int tpn = tqn % 9, icgn = (tqn / 9)*32;
                wreg = *(const uint4*)&g_wt4[tpn*(NF*16) + (icgn + wi_icl)*16 + 4*wi_c];
            }
            __syncthreads();
            int dtr = tap/3, dtc = tap - dtr*3;
            #pragma unroll
            for (int ks = 0; ks < 4; ks++) {
                int kl = ks*8;
                uint32_t a0 = wslab[(kl+t)*24   + g];
                uint32_t a1 = wslab[(kl+t)*24   + g + 8];
                uint32_t a2 = wslab[(kl+t+4)*24 + g];
                uint32_t a3 = wslab[(kl+t+4)*24 + g + 8];
                #pragma unroll
                for (int jj = 0; jj < 4; jj++) {
                    int jn = warp*4 + jj;
                    int jr = jn >> 1, jc = (jn & 1)*8;
                    const uint32_t* bp = &tileS[((jr+dtr)*18 + jc + g + dtc)*36 + kl + t];
                    uint32_t b0 = bp[0], b1 = bp[4];
                    MMA_TF32(acc[jj], a0,a1,a2,a3, b0,b1);
                }
            }
        }
    }

    #pragma unroll
    for (int jj = 0; jj < 4; jj++) {
        int jn = warp*4 + jj;
        int jr = jn >> 1, jc = (jn & 1)*8;
        int h = by*8 + jr;            // < 360
        int px = bx*16 + jc + 2*t;    // < 640
        #pragma unroll
        for (int mrow = 0; mrow < 2; mrow++) {
            int o = g + 8*mrow;
            if (o >= 12) continue;
            int co = o >> 2, s1 = (o >> 1) & 1, s2 = o & 1;
            float bv = sbias[o] + rgb_mean(co);
            float* dst = out + ((b*3+co)*720 + 2*h + s1)*1280;
            dst[2*px + s2]     = acc[jj][2*mrow]   + bv;
            dst[2*(px+1) + s2] = acc[jj][2*mrow+1] + bv;
        }
    }
}

// ---------------- launch ----------------
extern "C" void kernel_launch(void* const* d_in, const int* in_sizes, int n_in,
                              void* d_out, int out_size) {
    const float* x  = (const float*)d_in[0];
    const float* w1 = (const float*)d_in[1];
    const float* b1 = (const float*)d_in[2];
    const float* w2 = (const float*)d_in[3];
    const float* b2 = (const float*)d_in[4];
    const float* wk = (const float*)d_in[5];
    const float* bk = (const float*)d_in[6];
    const float* wb = (const float*)d_in[7];
    const float* bb = (const float*)d_in[8];
    const float* w3 = (const float*)d_in[9];
    const float* b3 = (const float*)d_in[10];
    const float* w4 = (const float*)d_in[11];
    const float* b4 = (const float*)d_in[12];
    float* out = (float*)d_out;

    kw_transpose<<<(25*FC*NF + 255)/256, 256>>>(w3, w2, w4);
    k12_conv12<<<BP/4, 128>>>(x, w1, b1, b2);
    k3_gemm<<<dim3(14, (BP+127)/128), 128>>>(wk, bk, wb, bb);
    k4_adapt<<<BP/2, 128>>>(x);
    k5_conv3<<<dim3((WP+15)/16, (HP+7)/8, B_), 128>>>(b3);
    k6_conv4<<<dim3(W_/16, H_/8, B_), 128>>>(b4, out);
}

// round 12
// speedup vs baseline: 1.2600x; 1.1038x over previous
#include <cuda_runtime.h>
#include <cstdint>

#define B_ 4
#define C_ 3
#define H_ 360
#define W_ 640
#define HP 364
#define WP 644
#define GH 52
#define GW 92
#define BP (B_*GH*GW)   /* 19136 patches */
#define FH 64           /* F_HEAD */
#define FC 32           /* F_CH  */
#define NF 64           /* N_FEATS */

// ---------------- scratch (device globals; no allocation allowed) ----------
__device__ __align__(16) float g_feat2[BP*FH*9];    // conv2 out: [p][oc*9+pos]
__device__ __align__(16) float g_kern [BP*FC*27];   // per-patch kernels [p][864]
__device__ __align__(16) float g_bias [BP*FC];      // per-patch bias [p][32]
__device__ __align__(16) uint32_t g_ymid[(size_t)B_*HP*WP*FC]; // k4 out, NHWC tf32 bits
__device__ __align__(16) uint32_t g_y3 [(size_t)B_*HP*WP*NF];  // k5 out, NHWC tf32 bits
__device__ __align__(16) uint32_t g_wt [25*FC*NF];  // conv3 w tf32 [tap][ic][oc]
__device__ __align__(16) uint32_t g_wt2[9*FH*FH];   // conv2 w tf32 [tap][ic][oc]
__device__ __align__(16) uint32_t g_wt4[9*NF*16];   // conv4 w tf32 [tap][ic][oc16]

__device__ __forceinline__ float rgb_mean(int c) {
    return (c == 0) ? 0.4488f*255.0f : (c == 1) ? 0.4371f*255.0f : 0.404f*255.0f;
}

__device__ __forceinline__ uint32_t tf32_bits(float f) {
    uint32_t u;
    asm("cvt.rna.tf32.f32 %0, %1;" : "=r"(u) : "f"(f));
    return u;
}

#define MMA_TF32(ACC, A0,A1,A2,A3, B0,B1) \
    asm volatile("mma.sync.aligned.m16n8k8.row.col.f32.tf32.tf32.f32 " \
        "{%0,%1,%2,%3}, {%4,%5,%6,%7}, {%8,%9}, {%0,%1,%2,%3};\n" \
        : "+f"((ACC)[0]), "+f"((ACC)[1]), "+f"((ACC)[2]), "+f"((ACC)[3]) \
        : "r"(A0), "r"(A1), "r"(A2), "r"(A3), "r"(B0), "r"(B1))

// ---------------- merged weight transpose (tf32 pre-conversion, 1 launch) ----
__global__ void kw_transpose(const float* __restrict__ w3,
                             const float* __restrict__ w2,
                             const float* __restrict__ w4) {
    int i = blockIdx.x*256 + threadIdx.x;
    if (i < 25*FC*NF) {
        int tap = i / (FC*NF);
        int rem = i - tap*(FC*NF);
        int ic = rem >> 6, oc = rem & 63;
        g_wt[i] = tf32_bits(w3[(oc*FC + ic)*25 + tap]);
    }
    if (i < 9*FH*FH) {
        int tap = i / (FH*FH);
        int rem = i - tap*(FH*FH);
        int ic = rem >> 6, oc = rem & 63;
        g_wt2[i] = tf32_bits(w2[(oc*FH + ic)*9 + tap]);
    }
    if (i < 9*NF*16) {
        int tap = i / (NF*16);
        int rem = i - tap*(NF*16);
        int ic = rem >> 4, oc = rem & 15;
        float v = (oc < 12) ? w4[(oc*NF + ic)*9 + tap] : 0.f;
        g_wt4[i] = tf32_bits(v);
    }
}

// ---------------- K12: FUSED conv1 (fp32, reg weights) + conv2 (tf32 mma).
__global__ void __launch_bounds__(128) k12_conv12(const float* __restrict__ x,
                                                  const float* __restrict__ w1,
                                                  const float* __restrict__ b1,
                                                  const float* __restrict__ b2) {
    __shared__ float sp[4][148];
    __shared__ float ws[FH*27];
    __shared__ float bs[FH];
    __shared__ __align__(16) uint32_t sf[4*25*68];    // [pl*25+pos][ic pad 68]
    __shared__ __align__(16) uint32_t wslab[64*72];   // [ic][oc pad 72]
    int tid = threadIdx.x;
    int p0 = blockIdx.x*4;
    int warp = tid >> 5, lane = tid & 31;
    int g = lane >> 2, t = lane & 3;
    int pl = warp;

    for (int i = tid; i < FH*27; i += 128) ws[i] = w1[i];
    if (tid < FH) bs[tid] = b1[tid];
    for (int i = tid; i < 4*147; i += 128) {
        int pp = i / 147, q = i - pp*147;
        int c = q/49, rr = q%49, ii = rr/7, jj = rr%7;
        int p = p0 + pp;
        int b = p/(GH*GW); int r = p%(GH*GW); int gi = r/GW, gj = r%GW;
        int h = gi*7 + ii, w = gj*7 + jj;
        float v = 0.f;
        if (h < H_ && w < W_) v = x[((b*C_+c)*H_ + h)*W_ + w] - rgb_mean(c);
        sp[pp][q] = v;
    }
    __syncthreads();
    {
        float wr0[27], wr1[27];
        #pragma unroll
        for (int k = 0; k < 27; k++) { wr0[k] = ws[lane*27+k]; wr1[k] = ws[(lane+32)*27+k]; }
        float bv0 = bs[lane], bv1 = bs[lane+32];
        #pragma unroll
        for (int q = 0; q < 25; q++) {
            int oy = q/5, ox = q%5;
            float a0 = bv0, a1 = bv1;
            #pragma unroll
            for (int c = 0; c < 3; c++)
                #pragma unroll
                for (int ky = 0; ky < 3; ky++)
                    #pragma unroll
                    for (int kx = 0; kx < 3; kx++) {
                        float tap = sp[pl][c*49 + (oy+ky)*7 + (ox+kx)];
                        int k = c*9 + ky*3 + kx;
                        a0 += tap*wr0[k];
                        a1 += tap*wr1[k];
                    }
            sf[(pl*25+q)*68 + lane]      = tf32_bits(fmaxf(a0, 0.f));
            sf[(pl*25+q)*68 + lane + 32] = tf32_bits(fmaxf(a1, 0.f));
        }
    }

    uint4 wreg[8];
    #pragma unroll
    for (int u = 0; u < 8; u++) {
        int i = tid + u*128;
        wreg[u] = *(const uint4*)&g_wt2[((i>>4)<<6) + 4*(i&15)];
    }
    __syncthreads();   // sf fully written

    int rB[5];
    #pragma unroll
    for (int j = 0; j < 5; j++) {
        int col = 8*j + g;
        int cc = (col < 36) ? col : 35;
        int plc = cc/9, pos = cc - plc*9;
        int oy = pos/3, ox = pos - oy*3;
        rB[j] = plc*25 + oy*5 + ox;
    }
    float acc[5][4];
    #pragma unroll
    for (int j = 0; j < 5; j++)
        #pragma unroll
        for (int q = 0; q < 4; q++) acc[j][q] = 0.f;

    for (int tap = 0; tap < 9; tap++) {
        if (tap) __syncthreads();
        #pragma unroll
        for (int u = 0; u < 8; u++) {
            int i = tid + u*128;
            *(uint4*)&wslab[(i>>4)*72 + 4*(i&15)] = wreg[u];
        }
        if (tap < 8) {
            #pragma unroll
            for (int u = 0; u < 8; u++) {
                int i = tid + u*128;
                wreg[u] = *(const uint4*)&g_wt2[(tap+1)*4096 + ((i>>4)<<6) + 4*(i&15)];
            }
        }
        __syncthreads();
        int dtr = tap/3, dtc = tap - dtr*3;
        int roff = (dtr*5 + dtc)*68;
        #pragma unroll
        for (int ks = 0; ks < 8; ks++) {
            int kl = ks*8;
            uint32_t a0 = wslab[(kl+t)*72   + 16*warp + g];
            uint32_t a1 = wslab[(kl+t)*72   + 16*warp + g + 8];
            uint32_t a2 = wslab[(kl+t+4)*72 + 16*warp + g];
            uint32_t a3 = wslab[(kl+t+4)*72 + 16*warp + g + 8];
            #pragma unroll
            for (int j = 0; j < 5; j++) {
                const uint32_t* bp = &sf[rB[j]*68 + roff + kl + t];
                uint32_t b0 = bp[0], b1 = bp[4];
                MMA_TF32(acc[j], a0,a1,a2,a3, b0,b1);
            }
        }
    }

    int oc0 = 16*warp + g;
    float bv0 = b2[oc0], bv1 = b2[oc0+8];
    #pragma unroll
    for (int j = 0; j < 5; j++) {
        #pragma unroll
        for (int h2 = 0; h2 < 2; h2++) {
            int col = 8*j + 2*t + h2;
            if (col >= 36) continue;
            int plc = col/9, pos = col - plc*9;
            float* d = g_feat2 + (size_t)(p0+plc)*576;
            d[oc0*9 + pos]     = fmaxf(acc[j][h2]   + bv0, 0.f);
            d[(oc0+8)*9 + pos] = fmaxf(acc[j][2+h2] + bv1, 0.f);
        }
    }
}

// ---------------- K3: fused GEMM C[BP][896] = feat2[BP][576] x [wk;wb]^T + [bk;bb]
__global__ void __launch_bounds__(128) k3_gemm(const float* __restrict__ wk,
                                               const float* __restrict__ bk,
                                               const float* __restrict__ wb,
                                               const float* __restrict__ bb) {
    __shared__ uint32_t As[128*36];
    __shared__ uint32_t Bs[64*36];
    int tid = threadIdx.x;
    int warp = tid >> 5, lane = tid & 31;
    int g = lane >> 2, t = lane & 3;
    int m0 = blockIdx.y*128, n0 = blockIdx.x*64;
    int c = tid & 7, r0 = tid >> 3;

    float acc[2][8][4];
    #pragma unroll
    for (int mt = 0; mt < 2; mt++)
        #pragma unroll
        for (int j = 0; j < 8; j++)
            #pragma unroll
            for (int q = 0; q < 4; q++) acc[mt][j][q] = 0.f;

    for (int k0 = 0; k0 < 576; k0 += 32) {
        __syncthreads();
        #pragma unroll
        for (int rr = r0; rr < 128; rr += 16) {
            int m = m0 + rr;
            float4 v = make_float4(0.f,0.f,0.f,0.f);
            if (m < BP) v = *(const float4*)&g_feat2[(size_t)m*576 + k0 + 4*c];
            uint32_t* dst = &As[rr*36 + 4*c];
            dst[0]=tf32_bits(v.x); dst[1]=tf32_bits(v.y);
            dst[2]=tf32_bits(v.z); dst[3]=tf32_bits(v.w);
        }
        #pragma unroll
        for (int rr = r0; rr < 64; rr += 16) {
            int n = n0 + rr;
            const float* src = (n < 864) ? &wk[(size_t)n*576] : &wb[(size_t)(n-864)*576];
            float4 v = *(const float4*)&src[k0 + 4*c];
            uint32_t* dst = &Bs[rr*36 + 4*c];
            dst[0]=tf32_bits(v.x); dst[1]=tf32_bits(v.y);
            dst[2]=tf32_bits(v.z); dst[3]=tf32_bits(v.w);
        }
        __syncthreads();
        #pragma unroll
        for (int ks = 0; ks < 4; ks++) {
            int kl = ks*8;
            uint32_t bf[8][2];
            #pragma unroll
            for (int j = 0; j < 8; j++) {
                bf[j][0] = Bs[(8*j+g)*36 + kl + t];
                bf[j][1] = Bs[(8*j+g)*36 + kl + t + 4];
            }
            #pragma unroll
            for (int mt = 0; mt < 2; mt++) {
                int mb = 32*warp + 16*mt;
                uint32_t a0 = As[(mb+g)*36   + kl + t];
                uint32_t a1 = As[(mb+g+8)*36 + kl + t];
                uint32_t a2 = As[(mb+g)*36   + kl + t + 4];
                uint32_t a3 = As[(mb+g+8)*36 + kl + t + 4];
                #pragma unroll
                for (int j = 0; j < 8; j++)
                    MMA_TF32(acc[mt][j], a0,a1,a2,a3, bf[j][0], bf[j][1]);
            }
        }
    }

    #pragma unroll
    for (int mt = 0; mt < 2; mt++) {
        int m = m0 + 32*warp + 16*mt + g;
        #pragma unroll
        for (int j = 0; j < 8; j++) {
            #pragma unroll
            for (int h2 = 0; h2 < 2; h2++) {
                int n = n0 + 8*j + 2*t + h2;
                float v0 = acc[mt][j][h2], v1 = acc[mt][j][2+h2];
                if (n < 864) {
                    float bv = bk[n];
                    if (m < BP)     g_kern[(size_t)m*864 + n]     = v0 + bv;
                    if (m+8 < BP)   g_kern[(size_t)(m+8)*864 + n] = v1 + bv;
                } else {
                    float bv = bb[n-864];
                    if (m < BP)     g_bias[(size_t)m*32 + (n-864)]     = v0 + bv;
                    if (m+8 < BP)   g_bias[(size_t)(m+8)*32 + (n-864)] = v1 + bv;
                }
            }
        }
    }
}

// ---------------- K4: adaptive per-patch 3x3 conv — 2 patches/block,
// float4 weight LDS ([32][28] padded smem), NHWC tf32 vectorized stores.
__global__ void __launch_bounds__(128) k4_adapt(const float* __restrict__ x) {
    __shared__ __align__(16) float ks[2][FC][28];
    __shared__ float bsm[2][FC];
    __shared__ float xs[2][C_*81];
    int p0 = blockIdx.x*2;
    int tid = threadIdx.x;
    for (int i = tid; i < 2*FC*27; i += 128) {
        int pp = i / (FC*27), k = i % (FC*27);
        ks[pp][k/27][k%27] = g_kern[(size_t)(p0+pp)*(FC*27) + k];
    }
    if (tid < 2*FC) bsm[tid>>5][tid&31] = g_bias[(size_t)(p0+(tid>>5))*FC + (tid&31)];
    for (int i = tid; i < 2*C_*81; i += 128) xs[i/243][i%243] = 0.f;
    __syncthreads();
    for (int i = tid; i < 2*C_*49; i += 128) {
        int pp = i/147, q = i%147;
        int c = q/49, rr = q%49, ii = rr/7, jj = rr%7;
        int p = p0 + pp;
        int b = p/(GH*GW); int r = p%(GH*GW); int gi = r/GW, gj = r%GW;
        int h = gi*7+ii, w = gj*7+jj;
        float v = 0.f;
        if (h < H_ && w < W_) v = x[((b*C_+c)*H_+h)*W_+w] - rgb_mean(c);
        xs[pp][c*81 + (ii+1)*9 + (jj+1)] = v;
    }
    __syncthreads();
    if (tid < 98) {
        int pl = tid/49, q = tid - pl*49;
        int i = q/7, j = q%7;
        float v[27];
        #pragma unroll
        for (int c = 0; c < 3; c++)
            #pragma unroll
            for (int di = 0; di < 3; di++)
                #pragma unroll
                for (int dj = 0; dj < 3; dj++)
                    v[c*9+di*3+dj] = xs[pl][c*81 + (i+di)*9 + (j+dj)];
        int p = p0 + pl;
        int b = p/(GH*GW); int r = p%(GH*GW); int gi = r/GW, gj = r%GW;
        int h = gi*7+i, w = gj*7+j;
        uint32_t o32[FC];
        for (int f = 0; f < FC; f++) {
            float wq[28];
            #pragma unroll
            for (int u = 0; u < 7; u++)
                *(float4*)&wq[4*u] = *(const float4*)&ks[pl][f][4*u];
            float acc = bsm[pl][f];
            #pragma unroll
            for (int k = 0; k < 27; k++) acc += wq[k]*v[k];
            o32[f] = tf32_bits(acc);
        }
        uint32_t* dst = &g_ymid[((size_t)(b*HP+h)*WP + w)*FC];
        #pragma unroll
        for (int u = 0; u < 8; u++)
            *(uint4*)&dst[4*u] = *(uint4*)&o32[4*u];
    }
}

// ---------------- K5: conv3 5x5 pad2, 32->64, relu — tf32 mma.
// NHWC tf32 g_ymid: tile staging is pure uint4 copy (no CVT).
// Epilogue stores NHWC tf32 g_y3.
__global__ void __launch_bounds__(128) k5_conv3(const float* __restrict__ b3) {
    __shared__ __align__(16) uint32_t tileS[12*20*36];
    __shared__ __align__(16) uint32_t wslab[32*72];
    __shared__ float sbias[NF];
    int b  = blockIdx.z;
    int by = blockIdx.y, bx = blockIdx.x;
    int tid = threadIdx.x;
    int warp = tid >> 5, lane = tid & 31;
    int g = lane >> 2, t = lane & 3;
    int gh0 = by*8 - 2, gw0 = bx*16 - 2;

    for (int i = tid; i < 240*8; i += 128) {
        int pos = i >> 3, c4 = i & 7;
        int r = pos / 20, c = pos - r*20;
        int hh = gh0 + r, ww = gw0 + c;
        uint4 v = make_uint4(0,0,0,0);
        if (hh >= 0 && hh < HP && ww >= 0 && ww < WP)
            v = *(const uint4*)&g_ymid[((size_t)(b*HP+hh)*WP + ww)*FC + 4*c4];
        *(uint4*)&tileS[pos*36 + 4*c4] = v;
    }
    if (tid < NF) sbias[tid] = b3[tid];

    float acc[16][4];
    #pragma unroll
    for (int j = 0; j < 16; j++)
        #pragma unroll
        for (int q = 0; q < 4; q++) acc[j][q] = 0.f;

    uint4 wreg[4];
    #pragma unroll
    for (int u = 0; u < 4; u++) {
        int i = tid + u*128;
        wreg[u] = *(const uint4*)&g_wt[((i>>4)<<6) + 4*(i&15)];
    }

    for (int tap = 0; tap < 25; tap++) {
        __syncthreads();
        #pragma unroll
        for (int u = 0; u < 4; u++) {
            int i = tid + u*128;
            *(uint4*)&wslab[(i>>4)*72 + 4*(i&15)] = wreg[u];
        }
        if (tap < 24) {
            #pragma unroll
            for (int u = 0; u < 4; u++) {
                int i = tid + u*128;
                wreg[u] = *(const uint4*)&g_wt[(tap+1)*2048 + ((i>>4)<<6) + 4*(i&15)];
            }
        }
        __syncthreads();
        int dtr = tap / 5, dtc = tap - dtr*5;
        #pragma unroll
        for (int ks = 0; ks < 4; ks++) {
            int ic0 = ks*8;
            uint32_t a0 = wslab[(ic0+t)*72   + 16*warp + g];
            uint32_t a1 = wslab[(ic0+t)*72   + 16*warp + g + 8];
            uint32_t a2 = wslab[(ic0+t+4)*72 + 16*warp + g];
            uint32_t a3 = wslab[(ic0+t+4)*72 + 16*warp + g + 8];
            #pragma unroll
            for (int j = 0; j < 16; j++) {
                int jr = j >> 1, jc = (j & 1)*8;
                const uint32_t* bp = &tileS[((jr+dtr)*20 + jc + g + dtc)*36 + ic0 + t];
                uint32_t b0 = bp[0], b1 = bp[4];
                MMA_TF32(acc[j], a0,a1,a2,a3, b0,b1);
            }
        }
    }

    int oc0 = 16*warp + g;
    float bv0 = sbias[oc0], bv1 = sbias[oc0 + 8];
    #pragma unroll
    for (int j = 0; j < 16; j++) {
        int jr = j >> 1, jc = (j & 1)*8;
        int py = by*8 + jr;
        if (py >= HP) continue;
        int px = bx*16 + jc + 2*t;
        #pragma unroll
        for (int h2 = 0; h2 < 2; h2++) {
            int pxx = px + h2;
            if (pxx >= WP) continue;
            uint32_t* dst = &g_y3[((size_t)(b*HP+py)*WP + pxx)*NF];
            dst[oc0]     = tf32_bits(fmaxf(acc[j][h2]   + bv0, 0.f));
            dst[oc0 + 8] = tf32_bits(fmaxf(acc[j][2+h2] + bv1, 0.f));
        }
    }
}

// ---------------- K6: conv4 3x3 pad1 (64->12) + pixel-shuffle — tf32 mma.
// NHWC tf32 g_y3: tile staging is pure uint4 copy.
__global__ void __launch_bounds__(128) k6_conv4(const float* __restrict__ b4,
                                                float* __restrict__ out) {
    __shared__ __align__(16) uint32_t tileS[180*36];   // 25.9 KB
    __shared__ __align__(16) uint32_t wslab[32*24];    //  3 KB
    __shared__ float sbias[16];
    int b  = blockIdx.z;
    int by = blockIdx.y, bx = blockIdx.x;
    int tid = threadIdx.x;
    int warp = tid >> 5, lane = tid & 31;
    int g = lane >> 2, t = lane & 3;
    int gh0 = by*8 - 1, gw0 = bx*16 - 1;
    if (tid < 16) sbias[tid] = (tid < 12) ? b4[tid] : 0.f;

    float acc[4][4];
    #pragma unroll
    for (int j = 0; j < 4; j++)
        #pragma unroll
        for (int q = 0; q < 4; q++) acc[j][q] = 0.f;

    int wi_icl = tid >> 2, wi_c = tid & 3;
    uint4 wreg = *(const uint4*)&g_wt4[wi_icl*16 + 4*wi_c];   // tq = 0

    for (int half = 0; half < 2; half++) {
        int icg = half*32;
        __syncthreads();   // WAR on tileS
        for (int i = tid; i < 180*8; i += 128) {
            int pos = i >> 3, c4 = i & 7;
            int r = pos / 18, c = pos - r*18;
            int hh = gh0 + r, ww = gw0 + c;
            uint4 v = make_uint4(0,0,0,0);
            if (hh >= 0 && ww >= 0)
                v = *(const uint4*)&g_y3[((size_t)(b*HP+hh)*WP + ww)*NF + icg + 4*c4];
            *(uint4*)&tileS[pos*36 + 4*c4] = v;
        }
        for (int tap = 0; tap < 9; tap++) {
            __syncthreads();   // WAR on wslab (first iter also covers tileS)
            *(uint4*)&wslab[wi_icl*24 + 4*wi_c] = wreg;
            int tq = half*9 + tap;
            if (tq < 17) {
                int tqn = tq + 1;
                int tpn = tqn % 9, icgn = (tqn / 9)*32;
                wreg = *(const uint4*)&g_wt4[tpn*(NF*16) + (icgn + wi_icl)*16 + 4*wi_c];
            }
            __syncthreads();
            int dtr = tap/3, dtc = tap - dtr*3;
            #pragma unroll
            for (int ks = 0; ks < 4; ks++) {
                int kl = ks*8;
                uint32_t a0 = wslab[(kl+t)*24   + g];
                uint32_t a1 = wslab[(kl+t)*24   + g + 8];
                uint32_t a2 = wslab[(kl+t+4)*24 + g];
                uint32_t a3 = wslab[(kl+t+4)*24 + g + 8];
                #pragma unroll
                for (int jj = 0; jj < 4; jj++) {
                    int jn = warp*4 + jj;
                    int jr = jn >> 1, jc = (jn & 1)*8;
                    const uint32_t* bp = &tileS[((jr+dtr)*18 + jc + g + dtc)*36 + kl + t];
                    uint32_t b0 = bp[0], b1 = bp[4];
                    MMA_TF32(acc[jj], a0,a1,a2,a3, b0,b1);
                }
            }
        }
    }

    #pragma unroll
    for (int jj = 0; jj < 4; jj++) {
        int jn = warp*4 + jj;
        int jr = jn >> 1, jc = (jn & 1)*8;
        int h = by*8 + jr;            // < 360
        int px = bx*16 + jc + 2*t;    // < 640
        #pragma unroll
        for (int mrow = 0; mrow < 2; mrow++) {
            int o = g + 8*mrow;
            if (o >= 12) continue;
            int co = o >> 2, s1 = (o >> 1) & 1, s2 = o & 1;
            float bv = sbias[o] + rgb_mean(co);
            float* dst = out + ((b*3+co)*720 + 2*h + s1)*1280;
            dst[2*px + s2]     = acc[jj][2*mrow]   + bv;
            dst[2*(px+1) + s2] = acc[jj][2*mrow+1] + bv;
        }
    }
}

// ---------------- launch ----------------
extern "C" void kernel_launch(void* const* d_in, const int* in_sizes, int n_in,
                              void* d_out, int out_size) {
    const float* x  = (const float*)d_in[0];
    const float* w1 = (const float*)d_in[1];
    const float* b1 = (const float*)d_in[2];
    const float* w2 = (const float*)d_in[3];
    const float* b2 = (const float*)d_in[4];
    const float* wk = (const float*)d_in[5];
    const float* bk = (const float*)d_in[6];
    const float* wb = (const float*)d_in[7];
    const float* bb = (const float*)d_in[8];
    const float* w3 = (const float*)d_in[9];
    const float* b3 = (const float*)d_in[10];
    const float* w4 = (const float*)d_in[11];
    const float* b4 = (const float*)d_in[12];
    float* out = (float*)d_out;

    kw_transpose<<<(25*FC*NF + 255)/256, 256>>>(w3, w2, w4);
    k12_conv12<<<BP/4, 128>>>(x, w1, b1, b2);
    k3_gemm<<<dim3(14, (BP+127)/128), 128>>>(wk, bk, wb, bb);
    k4_adapt<<<BP/2, 128>>>(x);
    k5_conv3<<<dim3((WP+15)/16, (HP+7)/8, B_), 128>>>(b3);
    k6_conv4<<<dim3(W_/16, H_/8, B_), 128>>>(b4, out);
}